// round 13
// baseline (speedup 1.0000x reference)
#include <cuda_runtime.h>
#include <cuda_fp16.h>
#include <math.h>
#include <stdint.h>

#define HIDDEN 2048
#define NQ 16
#define NKV 8
#define HD 128
#define SEQ 2048
#define BATCH 2
#define MROWS 4096
#define RANK 8
#define LORA_SC 2.0f
#define SM_SCALE 0.08838834764831845f
#define LOG2E 1.4426950408889634f

// ---------------- scratch (fp16 staged tensors) --------------------------------
__device__ __half g_q[8388608];      // [B][NQ][S][D]  (pre-scaled by SM_SCALE*LOG2E)
__device__ __half g_k[4194304];      // [B][NKV][S][D]
__device__ __half g_vT[4194304];     // [B][NKV][D][S]
__device__ __half g_attn[8388608];   // [B][NQ][S][D]
__device__ __half g_xr[8388608];     // fp16 x
__device__ __half g_wq[4194304];
__device__ __half g_wk[2097152];
__device__ __half g_wv[2097152];
__device__ __half g_wo[4194304];
__device__ float g_tq[MROWS * RANK];
__device__ float g_tk[MROWS * RANK];
__device__ float g_tv[MROWS * RANK];
__device__ float g_to[MROWS * RANK];
__device__ float g_cos[SEQ * 64];
__device__ float g_sin[SEQ * 64];

// ---------------- helpers -----------------------------------------------------
__device__ __forceinline__ void mma16(float* c, const uint4& a, uint32_t b0, uint32_t b1) {
    asm volatile(
        "mma.sync.aligned.m16n8k16.row.col.f32.f16.f16.f32 "
        "{%0,%1,%2,%3}, {%4,%5,%6,%7}, {%8,%9}, {%0,%1,%2,%3};\n"
        : "+f"(c[0]), "+f"(c[1]), "+f"(c[2]), "+f"(c[3])
        : "r"(a.x), "r"(a.y), "r"(a.z), "r"(a.w), "r"(b0), "r"(b1));
}

__device__ __forceinline__ uint32_t s2u(const void* p) {
    uint32_t r;
    asm("{ .reg .u64 t; cvta.to.shared.u64 t, %1; cvt.u32.u64 %0, t; }"
        : "=r"(r) : "l"(p));
    return r;
}

#define CPA16(dst, src) \
    asm volatile("cp.async.cg.shared.global [%0], [%1], 16;\n" ::"r"(dst), "l"(src))
#define CPC() asm volatile("cp.async.commit_group;\n")
#define CPW(n) asm volatile("cp.async.wait_group %0;\n" ::"n"(n))

__device__ __forceinline__ void ldsm4(uint4& d, uint32_t a) {
    asm volatile("ldmatrix.sync.aligned.m8n8.x4.shared.b16 {%0,%1,%2,%3}, [%4];\n"
                 : "=r"(d.x), "=r"(d.y), "=r"(d.z), "=r"(d.w)
                 : "r"(a));
}

__device__ __forceinline__ uint32_t h2u(__half2 h) { return *(uint32_t*)&h; }

// ---------------- merged prologue ----------------------------------------------
// blocks [0,256): LoRA down Q/K/V + x fp16 conversion (16 rows/blk, 2 rows/warp)
// blocks [256, 12544): weight fp16 conversion (3145728 float4 tasks)
// blocks [12544, 13056): rope table (131072 entries)
__global__ void __launch_bounds__(256) prep_kernel(const float* __restrict__ x,
                                                   const float* __restrict__ qA,
                                                   const float* __restrict__ kA,
                                                   const float* __restrict__ vA,
                                                   const float* __restrict__ Wq,
                                                   const float* __restrict__ Wk,
                                                   const float* __restrict__ Wv,
                                                   const float* __restrict__ Wo) {
    int blk = blockIdx.x;
    int tid = threadIdx.x;
    if (blk >= 12544) {
        int idx = (blk - 12544) * 256 + tid;
        if (idx < SEQ * 64) {
            int s = idx >> 6, f = idx & 63;
            double inv = pow(10000.0, -(double)(2 * f) / 128.0);
            double ang = (double)s * inv;
            g_cos[idx] = (float)cos(ang);
            g_sin[idx] = (float)sin(ang);
        }
        return;
    }
    if (blk >= 256) {
        int i = (blk - 256) * 256 + tid;
        const float4* src;
        __half* dst;
        int j;
        if (i < 1048576) { src = (const float4*)Wq; dst = g_wq; j = i; }
        else if (i < 1572864) { src = (const float4*)Wk; dst = g_wk; j = i - 1048576; }
        else if (i < 2097152) { src = (const float4*)Wv; dst = g_wv; j = i - 1572864; }
        else { src = (const float4*)Wo; dst = g_wo; j = i - 2097152; }
        float4 v = src[j];
        __half2* d2 = (__half2*)(dst + (size_t)j * 4);
        d2[0] = __floats2half2_rn(v.x, v.y);
        d2[1] = __floats2half2_rn(v.z, v.w);
        return;
    }
    // ---- LoRA down for QKV + x conversion (16 rows, 2 per warp) ----
    __shared__ float Ach[24][256];
    __shared__ float xch[16][256];
    int lane = tid & 31, w = tid >> 5;
    int m0 = blk * 16;
    float part[2][24];
#pragma unroll
    for (int rr = 0; rr < 2; rr++)
#pragma unroll
        for (int r = 0; r < 24; r++) part[rr][r] = 0.f;

    for (int kc = 0; kc < 8; kc++) {
        int kb = kc * 256;
#pragma unroll
        for (int i = 0; i < 6; i++) {
            int idx = i * 256 + tid;
            int r = idx >> 6, c4 = (idx & 63) << 2;
            const float* A = (r < 8) ? qA + (size_t)r * HIDDEN
                           : (r < 16) ? kA + (size_t)(r - 8) * HIDDEN
                                      : vA + (size_t)(r - 16) * HIDDEN;
            *(float4*)&Ach[r][c4] = *(const float4*)&A[kb + c4];
        }
#pragma unroll
        for (int i = 0; i < 4; i++) {
            int idx = i * 256 + tid;
            int r = idx >> 6, c4 = (idx & 63) << 2;
            float4 v = *(const float4*)&x[(size_t)(m0 + r) * HIDDEN + kb + c4];
            *(float4*)&xch[r][c4] = v;
            __half2* o = (__half2*)&g_xr[(size_t)(m0 + r) * HIDDEN + kb + c4];
            o[0] = __floats2half2_rn(v.x, v.y);
            o[1] = __floats2half2_rn(v.z, v.w);
        }
        __syncthreads();
        float xv0[8], xv1[8];
#pragma unroll
        for (int i = 0; i < 8; i++) {
            xv0[i] = xch[2 * w][lane + 32 * i];
            xv1[i] = xch[2 * w + 1][lane + 32 * i];
        }
#pragma unroll
        for (int r = 0; r < 24; r++) {
            float s0 = 0.f, s1 = 0.f;
#pragma unroll
            for (int i = 0; i < 8; i++) {
                float a = Ach[r][lane + 32 * i];
                s0 += xv0[i] * a;
                s1 += xv1[i] * a;
            }
            part[0][r] += s0;
            part[1][r] += s1;
        }
        __syncthreads();
    }
#pragma unroll
    for (int rr = 0; rr < 2; rr++) {
#pragma unroll
        for (int r = 0; r < 24; r++) {
            float v = part[rr][r];
#pragma unroll
            for (int o = 16; o > 0; o >>= 1) v += __shfl_xor_sync(0xffffffffu, v, o);
            part[rr][r] = v;
        }
        if (lane == 0) {
            int m = m0 + 2 * w + rr;
#pragma unroll
            for (int r = 0; r < 8; r++) {
                g_tq[m * RANK + r] = part[rr][r];
                g_tk[m * RANK + r] = part[rr][8 + r];
                g_tv[m * RANK + r] = part[rr][16 + r];
            }
        }
    }
}

// ---------------- LoRA down: O, 8 rows/block ----------------------------------
__global__ void __launch_bounds__(256) lora_down_o2(const float* __restrict__ oA) {
    __shared__ float Ach[8][256];
    __shared__ float xch[8][256];
    int tid = threadIdx.x, lane = tid & 31, w = tid >> 5;
    int m0 = blockIdx.x * 8;
    float part[8];
#pragma unroll
    for (int r = 0; r < 8; r++) part[r] = 0.f;

    for (int kc = 0; kc < 8; kc++) {
        int kb = kc * 256;
#pragma unroll
        for (int i = 0; i < 2; i++) {
            int idx = i * 256 + tid;
            int r = idx >> 6, c4 = (idx & 63) << 2;
            *(float4*)&Ach[r][c4] = *(const float4*)&oA[(size_t)r * (NQ * HD) + kb + c4];
            int m = m0 + r, b = m >> 11, s = m & 2047;
            int k = kb + c4, h = k >> 7, d = k & 127;
            const __half2* src =
                (const __half2*)&g_attn[(((size_t)(b * NQ + h)) * SEQ + s) * HD + d];
            float2 f0 = __half22float2(src[0]);
            float2 f1 = __half22float2(src[1]);
            *(float4*)&xch[r][c4] = make_float4(f0.x, f0.y, f1.x, f1.y);
        }
        __syncthreads();
        float xv[8];
#pragma unroll
        for (int i = 0; i < 8; i++) xv[i] = xch[w][lane + 32 * i];
#pragma unroll
        for (int r = 0; r < 8; r++) {
            float s = 0.f;
#pragma unroll
            for (int i = 0; i < 8; i++) s += xv[i] * Ach[r][lane + 32 * i];
            part[r] += s;
        }
        __syncthreads();
    }
#pragma unroll
    for (int r = 0; r < 8; r++) {
        float v = part[r];
#pragma unroll
        for (int o = 16; o > 0; o >>= 1) v += __shfl_xor_sync(0xffffffffu, v, o);
        part[r] = v;
    }
    if (lane == 0) {
        int m = m0 + w;
#pragma unroll
        for (int r = 0; r < 8; r++) g_to[m * RANK + r] = part[r];
    }
}

// ---------------- fp16 GEMM: cp.async + ldmatrix + m16n8k16 (R7 config) --------
#define GEMM_SMEM 65536

template <int IS_O>
__global__ void __launch_bounds__(256, 2) gemm6_kernel(
    const float* __restrict__ qBp, const float* __restrict__ kBp,
    const float* __restrict__ vBp, float* __restrict__ Out) {
    extern __shared__ uint32_t smw[];
    const int tid = threadIdx.x, lane = tid & 31, wid = tid >> 5;
    const int g = lane >> 2, tig = lane & 3;
    const int wm = (wid & 3) * 32, wn = (wid >> 2) * 64;
    const int m0 = blockIdx.y * 128;
    const int nb = blockIdx.x;

    const __half* W;
    const float *U, *T;
    int which, nrel0;
    if (IS_O) {
        which = 3; nrel0 = nb * 128;
        W = g_wo + (size_t)nrel0 * HIDDEN; U = qBp + nrel0 * RANK; T = g_to;
    } else if (nb < 16) {
        which = 0; nrel0 = nb * 128;
        W = g_wq + (size_t)nrel0 * HIDDEN; U = qBp + nrel0 * RANK; T = g_tq;
    } else if (nb < 24) {
        which = 1; nrel0 = nb * 128 - 2048;
        W = g_wk + (size_t)nrel0 * HIDDEN; U = kBp + nrel0 * RANK; T = g_tk;
    } else {
        which = 2; nrel0 = nb * 128 - 3072;
        W = g_wv + (size_t)nrel0 * HIDDEN; U = vBp + nrel0 * RANK; T = g_tv;
    }

    const uint32_t smb = s2u(smw);

    const int fr = tid >> 1;
    const int fj0 = (tid & 1) * 2;
    const int fsw = (fr >> 1) & 3;
    const __half* srcB = W + (size_t)fr * HIDDEN;
    size_t aoff;
    if (IS_O) {
        int m = m0 + fr, b = m >> 11, s = m & 2047;
        aoff = (((size_t)(b * NQ)) * SEQ + s) * HD;
    } else {
        aoff = (size_t)(m0 + fr) * HIDDEN;
    }

    auto fill = [&](int st, int kc) {
        uint32_t dA = smb + (uint32_t)st * 8192u + (uint32_t)fr * 64u;
#pragma unroll
        for (int u = 0; u < 2; u++) {
            int j = fj0 + u;
            int k = kc * 32 + j * 8;
            const char* sA;
            if (IS_O) {
                int hh = k >> 7, dd = k & 127;
                sA = (const char*)(g_attn + aoff + (size_t)hh * SEQ * HD + dd);
            } else {
                sA = (const char*)(g_xr + aoff + k);
            }
            uint32_t dsw = (uint32_t)((j ^ fsw) << 4);
            CPA16(dA + dsw, sA);
            CPA16(dA + 32768u + dsw, (const char*)(srcB + k));
        }
    };

    const int rowAoff = (lane & 7) + ((lane >> 3) & 1) * 8;
    const int hiA = lane >> 4;
    const int swA = (rowAoff >> 1) & 3;
    const int rowBoff = (lane & 7) + ((lane >> 4) << 3);
    const int hiB = (lane >> 3) & 1;
    const int swB = (rowBoff >> 1) & 3;
    uint32_t aAddr[2], bAddr[4];
#pragma unroll
    for (int mt = 0; mt < 2; mt++)
        aAddr[mt] = smb + (uint32_t)((wm + mt * 16 + rowAoff) * 64);
#pragma unroll
    for (int p = 0; p < 4; p++)
        bAddr[p] = smb + 32768u + (uint32_t)((wn + p * 16 + rowBoff) * 64);

    float acc[2][8][4];
#pragma unroll
    for (int a = 0; a < 2; a++)
#pragma unroll
        for (int b2 = 0; b2 < 8; b2++)
#pragma unroll
            for (int c = 0; c < 4; c++) acc[a][b2][c] = 0.f;

    fill(0, 0); CPC();
    fill(1, 1); CPC();
    fill(2, 2); CPC();

    const int NKC = HIDDEN / 32;   // 64
    for (int kc = 0; kc < NKC; kc++) {
        CPW(2);
        __syncthreads();
        if (kc + 3 < NKC) { fill((kc + 3) & 3, kc + 3); CPC(); } else { CPC(); }
        uint32_t sb = (uint32_t)((kc & 3) * 8192);
#pragma unroll
        for (int c = 0; c < 2; c++) {
            uint4 Af0, Af1;
            uint32_t ga = (uint32_t)((((2 * c + hiA) ^ swA) << 4));
            ldsm4(Af0, aAddr[0] + sb + ga);
            ldsm4(Af1, aAddr[1] + sb + ga);
            uint32_t gb = (uint32_t)((((2 * c + hiB) ^ swB) << 4));
#pragma unroll
            for (int p = 0; p < 4; p++) {
                uint4 Bf;
                ldsm4(Bf, bAddr[p] + sb + gb);
                mma16(acc[0][2 * p],     Af0, Bf.x, Bf.y);
                mma16(acc[0][2 * p + 1], Af0, Bf.z, Bf.w);
                mma16(acc[1][2 * p],     Af1, Bf.x, Bf.y);
                mma16(acc[1][2 * p + 1], Af1, Bf.z, Bf.w);
            }
        }
    }

    // LoRA rank-8 tail
    __syncthreads();
    {
        int r = tid & 127;
        const float* src;
        float sc;
        uint32_t base;
        if (tid < 128) { src = T + (size_t)(m0 + r) * RANK; sc = 1.f; base = 0; }
        else           { src = U + (size_t)r * RANK; sc = LORA_SC; base = 8192; }
        __half2 h0 = __floats2half2_rn(src[0] * sc, src[1] * sc);
        __half2 h1 = __floats2half2_rn(src[2] * sc, src[3] * sc);
        __half2 h2 = __floats2half2_rn(src[4] * sc, src[5] * sc);
        __half2 h3 = __floats2half2_rn(src[6] * sc, src[7] * sc);
        int sw = (r >> 1) & 3;
        uint32_t w0 = base + r * 16 + ((0 ^ sw) << 2);
        uint32_t w1 = base + r * 16 + ((1 ^ sw) << 2);
        smw[w0 + 0] = h2u(h0); smw[w0 + 1] = h2u(h1);
        smw[w0 + 2] = h2u(h2); smw[w0 + 3] = h2u(h3);
        smw[w1 + 0] = 0; smw[w1 + 1] = 0; smw[w1 + 2] = 0; smw[w1 + 3] = 0;
    }
    __syncthreads();
    {
        uint4 Af0, Af1;
        uint32_t ga = (uint32_t)(((hiA ^ swA) << 4));
        ldsm4(Af0, aAddr[0] + ga);
        ldsm4(Af1, aAddr[1] + ga);
        uint32_t gb = (uint32_t)(((hiB ^ swB) << 4));
#pragma unroll
        for (int p = 0; p < 4; p++) {
            uint4 Bf;
            ldsm4(Bf, bAddr[p] + gb);
            mma16(acc[0][2 * p],     Af0, Bf.x, Bf.y);
            mma16(acc[0][2 * p + 1], Af0, Bf.z, Bf.w);
            mma16(acc[1][2 * p],     Af1, Bf.x, Bf.y);
            mma16(acc[1][2 * p + 1], Af1, Bf.z, Bf.w);
        }
    }

    // epilogue
#pragma unroll
    for (int mt = 0; mt < 2; mt++) {
#pragma unroll
        for (int rr = 0; rr < 2; rr++) {
            int m = m0 + wm + mt * 16 + g + rr * 8;
            int s = m & 2047, b = m >> 11;
#pragma unroll
            for (int ni = 0; ni < 8; ni++) {
                int nrel = nrel0 + wn + ni * 8 + 2 * tig;
                float v0 = acc[mt][ni][rr * 2 + 0];
                float v1 = acc[mt][ni][rr * 2 + 1];
                int d = nrel & 127;
                if (which <= 1) {
                    int f = d >> 1;
                    float c = g_cos[s * 64 + f], sn = g_sin[s * 64 + f];
                    float t0 = v0 * c - v1 * sn;
                    v1 = v0 * sn + v1 * c;
                    v0 = t0;
                }
                if (which == 3) {
                    *(float2*)&Out[(size_t)m * HIDDEN + nrel] = make_float2(v0, v1);
                } else if (which == 0) {
                    *(__half2*)&g_q[(((size_t)(b * NQ + (nrel >> 7))) * SEQ + s) * HD + d] =
                        __floats2half2_rn(v0 * (SM_SCALE * LOG2E), v1 * (SM_SCALE * LOG2E));
                } else if (which == 1) {
                    *(__half2*)&g_k[(((size_t)(b * NKV + (nrel >> 7))) * SEQ + s) * HD + d] =
                        __floats2half2_rn(v0, v1);
                } else {
                    __half* vb = g_vT + (((size_t)(b * NKV + (nrel >> 7))) * HD + d) * SEQ;
                    vb[s] = __float2half_rn(v0);
                    vb[SEQ + s] = __float2half_rn(v1);
                }
            }
        }
    }
}

// ---------------- fp16 flash attention (P in registers, exp2 softmax) ----------
// smem (bytes): Q [0,32768) | K st: 32768 + st*16384 | V st: 65536 + st*16384
#define FL_SMEM 98304

__global__ void __launch_bounds__(256, 2) flash_kernel() {
    extern __shared__ uint32_t sm[];
    const int tid = threadIdx.x, lane = tid & 31, wid = tid >> 5;
    const int g = lane >> 2, tig = lane & 3;
    int qb = (gridDim.x - 1) - blockIdx.x;
    int bh = blockIdx.y;
    int b = bh >> 4, h = bh & 15, kvh = h >> 1;
    const __half* Qb = g_q + ((size_t)(b * NQ + h)) * SEQ * HD;
    const __half* Kb = g_k + ((size_t)(b * NKV + kvh)) * SEQ * HD;
    const __half* Vb = g_vT + ((size_t)(b * NKV + kvh)) * HD * SEQ;
    int q0 = qb * 128, rb0 = wid * 16;
    const uint32_t smb = s2u(sm);

    const int rowAoff = (lane & 7) + ((lane >> 3) & 1) * 8;
    const int hiA = lane >> 4;
    const int swA = rowAoff & 7;
    const int rowBoff = (lane & 7) + ((lane >> 4) << 3);
    const int hiB = (lane >> 3) & 1;
    const int swB = rowBoff & 7;

    const uint32_t qA_base = smb + (uint32_t)((rb0 + rowAoff) * 256);
    uint32_t kB_base[4], vB_base[8];
#pragma unroll
    for (int p = 0; p < 4; p++)
        kB_base[p] = smb + 32768u + (uint32_t)((p * 16 + rowBoff) * 256);
#pragma unroll
    for (int p = 0; p < 8; p++)
        vB_base[p] = smb + 65536u + (uint32_t)((p * 16 + rowBoff) * 128);

#pragma unroll
    for (int i = 0; i < 8; i++) {
        int gid = i * 256 + tid;
        int r = gid >> 4, j = gid & 15;
        CPA16(smb + (uint32_t)(r * 256 + ((j ^ (r & 7)) << 4)),
              (const char*)(Qb + (size_t)(q0 + r) * HD + j * 8));
    }
    CPC();
    auto fillKV = [&](int kt, int st) {
        int k0 = kt * 64;
        uint32_t kst = smb + 32768u + (uint32_t)st * 16384u;
        uint32_t vst = smb + 65536u + (uint32_t)st * 16384u;
#pragma unroll
        for (int i = 0; i < 4; i++) {
            int gid = i * 256 + tid;
            int r = gid >> 4, j = gid & 15;
            CPA16(kst + (uint32_t)(r * 256 + ((j ^ (r & 7)) << 4)),
                  (const char*)(Kb + (size_t)(k0 + r) * HD + j * 8));
        }
#pragma unroll
        for (int i = 0; i < 4; i++) {
            int gid = i * 256 + tid;
            int rv = gid >> 3, jv = gid & 7;
            CPA16(vst + (uint32_t)(rv * 128 + ((jv ^ (rv & 7)) << 4)),
                  (const char*)(Vb + (size_t)rv * SEQ + k0 + jv * 8));
        }
    };
    fillKV(0, 0);
    CPC();

    float O[16][4];
#pragma unroll
    for (int i = 0; i < 16; i++)
#pragma unroll
        for (int j = 0; j < 4; j++) O[i][j] = 0.f;
    float mrow[2] = {-1e30f, -1e30f}, lrow[2] = {0.f, 0.f};

    int ktmax = 2 * qb + 1;
    for (int kt = 0; kt <= ktmax; kt++) {
        __syncthreads();
        if (kt < ktmax) { fillKV(kt + 1, (kt + 1) & 1); CPC(); } else { CPC(); }
        CPW(1);
        __syncthreads();
        uint32_t ksb = (kt & 1) ? 16384u : 0u;
        int k0 = kt * 64;

        float sacc[8][4];
#pragma unroll
        for (int i = 0; i < 8; i++)
#pragma unroll
            for (int j = 0; j < 4; j++) sacc[i][j] = 0.f;
#pragma unroll
        for (int c = 0; c < 8; c++) {
            uint4 Qf;
            ldsm4(Qf, qA_base + (uint32_t)((((2 * c + hiA) ^ swA) << 4)));
            uint32_t gb = (uint32_t)((((2 * c + hiB) ^ swB) << 4));
#pragma unroll
            for (int p = 0; p < 4; p++) {
                uint4 Kf;
                ldsm4(Kf, kB_base[p] + ksb + gb);
                mma16(sacc[2 * p],     Qf, Kf.x, Kf.y);
                mma16(sacc[2 * p + 1], Qf, Kf.z, Kf.w);
            }
        }
        if (kt >= 2 * qb) {
#pragma unroll
            for (int ni = 0; ni < 8; ni++)
#pragma unroll
                for (int j = 0; j < 4; j++) {
                    int col = k0 + ni * 8 + 2 * tig + (j & 1);
                    int row = q0 + rb0 + g + ((j >> 1) << 3);
                    if (col > row) sacc[ni][j] = -1e30f;
                }
        }
        // online softmax (exp2 domain); P stays in sacc registers
#pragma unroll
        for (int rr = 0; rr < 2; rr++) {
            float mx = -1e30f;
#pragma unroll
            for (int ni = 0; ni < 8; ni++)
                mx = fmaxf(mx, fmaxf(sacc[ni][rr * 2], sacc[ni][rr * 2 + 1]));
            mx = fmaxf(mx, __shfl_xor_sync(0xffffffffu, mx, 1));
            mx = fmaxf(mx, __shfl_xor_sync(0xffffffffu, mx, 2));
            float mnew = fmaxf(mrow[rr], mx);
            float corr = exp2f(mrow[rr] - mnew);
            float rs = 0.f;
#pragma unroll
            for (int ni = 0; ni < 8; ni++) {
                float p0 = exp2f(sacc[ni][rr * 2] - mnew);
                float p1 = exp2f(sacc[ni][rr * 2 + 1] - mnew);
                sacc[ni][rr * 2] = p0;
                sacc[ni][rr * 2 + 1] = p1;
                rs += p0 + p1;
            }
            rs += __shfl_xor_sync(0xffffffffu, rs, 1);
            rs += __shfl_xor_sync(0xffffffffu, rs, 2);
            lrow[rr] = lrow[rr] * corr + rs;
            mrow[rr] = mnew;
#pragma unroll
            for (int ni = 0; ni < 16; ni++) {
                O[ni][rr * 2] *= corr;
                O[ni][rr * 2 + 1] *= corr;
            }
        }
        // O += P @ V  — P consumed directly from sacc (C-frag == A-frag layout)
#pragma unroll
        for (int t = 0; t < 4; t++) {
            uint4 Pf;
            Pf.x = h2u(__floats2half2_rn(sacc[2 * t][0],     sacc[2 * t][1]));
            Pf.y = h2u(__floats2half2_rn(sacc[2 * t][2],     sacc[2 * t][3]));
            Pf.z = h2u(__floats2half2_rn(sacc[2 * t + 1][0], sacc[2 * t + 1][1]));
            Pf.w = h2u(__floats2half2_rn(sacc[2 * t + 1][2], sacc[2 * t + 1][3]));
            uint32_t gb = (uint32_t)((((2 * t + hiB) ^ swB) << 4));
#pragma unroll
            for (int p = 0; p < 8; p++) {
                uint4 Vf;
                ldsm4(Vf, vB_base[p] + ksb + gb);
                mma16(O[2 * p],     Pf, Vf.x, Vf.y);
                mma16(O[2 * p + 1], Pf, Vf.z, Vf.w);
            }
        }
    }

    __half* Ob = g_attn + ((size_t)(b * NQ + h)) * SEQ * HD;
#pragma unroll
    for (int rr = 0; rr < 2; rr++) {
        float inv = 1.f / lrow[rr];
        int r = q0 + rb0 + g + rr * 8;
#pragma unroll
        for (int ni = 0; ni < 16; ni++) {
            *(__half2*)&Ob[(size_t)r * HD + ni * 8 + 2 * tig] =
                __floats2half2_rn(O[ni][rr * 2] * inv, O[ni][rr * 2 + 1] * inv);
        }
    }
}

// ---------------- launch ------------------------------------------------------
extern "C" void kernel_launch(void* const* d_in, const int* in_sizes, int n_in,
                              void* d_out, int out_size) {
    const float* x  = (const float*)d_in[0];
    const float* Wq = (const float*)d_in[1];
    const float* Wk = (const float*)d_in[2];
    const float* Wv = (const float*)d_in[3];
    const float* Wo = (const float*)d_in[4];
    const float* qA = (const float*)d_in[5];
    const float* qB = (const float*)d_in[6];
    const float* kA = (const float*)d_in[7];
    const float* kB = (const float*)d_in[8];
    const float* vA = (const float*)d_in[9];
    const float* vB = (const float*)d_in[10];
    const float* oA = (const float*)d_in[11];
    const float* oB = (const float*)d_in[12];
    float* out = (float*)d_out;

    cudaFuncSetAttribute(gemm6_kernel<0>, cudaFuncAttributeMaxDynamicSharedMemorySize, GEMM_SMEM);
    cudaFuncSetAttribute(gemm6_kernel<1>, cudaFuncAttributeMaxDynamicSharedMemorySize, GEMM_SMEM);
    cudaFuncSetAttribute(flash_kernel, cudaFuncAttributeMaxDynamicSharedMemorySize, FL_SMEM);

    prep_kernel<<<13056, 256>>>(x, qA, kA, vA, Wq, Wk, Wv, Wo);

    gemm6_kernel<0><<<dim3(32, 32), 256, GEMM_SMEM>>>(qB, kB, vB, nullptr);

    flash_kernel<<<dim3(SEQ / 128, BATCH * NQ), 256, FL_SMEM>>>();

    lora_down_o2<<<512, 256>>>(oA);
    gemm6_kernel<1><<<dim3(16, 32), 256, GEMM_SMEM>>>(oB, nullptr, nullptr, out);
}

// round 14
// speedup vs baseline: 1.5217x; 1.5217x over previous
#include <cuda_runtime.h>
#include <cuda_fp16.h>
#include <math.h>
#include <stdint.h>

#define HIDDEN 2048
#define NQ 16
#define NKV 8
#define HD 128
#define SEQ 2048
#define BATCH 2
#define MROWS 4096
#define RANK 8
#define LORA_SC 2.0f
#define SM_SCALE 0.08838834764831845f
#define LOG2E 1.4426950408889634f

// ---------------- scratch (fp16 staged tensors) --------------------------------
__device__ __half g_q[8388608];      // [B][NQ][S][D]  (pre-scaled by SM_SCALE*LOG2E)
__device__ __half g_k[4194304];      // [B][NKV][S][D]
__device__ __half g_vT[4194304];     // [B][NKV][D][S]
__device__ __half g_attn[8388608];   // [B][NQ][S][D]
__device__ __half g_xr[8388608];     // fp16 x
__device__ __half g_wq[4194304];
__device__ __half g_wk[2097152];
__device__ __half g_wv[2097152];
__device__ __half g_wo[4194304];
__device__ float g_tq[MROWS * RANK];
__device__ float g_tk[MROWS * RANK];
__device__ float g_tv[MROWS * RANK];
__device__ float g_to[MROWS * RANK];
__device__ float g_cos[SEQ * 64];
__device__ float g_sin[SEQ * 64];

// ---------------- helpers -----------------------------------------------------
__device__ __forceinline__ void mma16(float* c, const uint4& a, uint32_t b0, uint32_t b1) {
    asm volatile(
        "mma.sync.aligned.m16n8k16.row.col.f32.f16.f16.f32 "
        "{%0,%1,%2,%3}, {%4,%5,%6,%7}, {%8,%9}, {%0,%1,%2,%3};\n"
        : "+f"(c[0]), "+f"(c[1]), "+f"(c[2]), "+f"(c[3])
        : "r"(a.x), "r"(a.y), "r"(a.z), "r"(a.w), "r"(b0), "r"(b1));
}

__device__ __forceinline__ uint32_t s2u(const void* p) {
    uint32_t r;
    asm("{ .reg .u64 t; cvta.to.shared.u64 t, %1; cvt.u32.u64 %0, t; }"
        : "=r"(r) : "l"(p));
    return r;
}

#define CPA16(dst, src) \
    asm volatile("cp.async.cg.shared.global [%0], [%1], 16;\n" ::"r"(dst), "l"(src))
#define CPC() asm volatile("cp.async.commit_group;\n")
#define CPW(n) asm volatile("cp.async.wait_group %0;\n" ::"n"(n))

__device__ __forceinline__ void ldsm4(uint4& d, uint32_t a) {
    asm volatile("ldmatrix.sync.aligned.m8n8.x4.shared.b16 {%0,%1,%2,%3}, [%4];\n"
                 : "=r"(d.x), "=r"(d.y), "=r"(d.z), "=r"(d.w)
                 : "r"(a));
}

__device__ __forceinline__ uint32_t h2u(__half2 h) { return *(uint32_t*)&h; }

// ---------------- merged prologue ----------------------------------------------
// blocks [0,512): LoRA down-projection for Q/K/V + x fp16 conversion (8 rows/blk)
// blocks [512, 12800): weight fp16 conversion (3145728 float4 tasks)
// blocks [12800, 13312): rope table (131072 entries)
__global__ void __launch_bounds__(256) prep_kernel(const float* __restrict__ x,
                                                   const float* __restrict__ qA,
                                                   const float* __restrict__ kA,
                                                   const float* __restrict__ vA,
                                                   const float* __restrict__ Wq,
                                                   const float* __restrict__ Wk,
                                                   const float* __restrict__ Wv,
                                                   const float* __restrict__ Wo) {
    int blk = blockIdx.x;
    int tid = threadIdx.x;
    if (blk >= 12800) {
        int idx = (blk - 12800) * 256 + tid;
        if (idx < SEQ * 64) {
            int s = idx >> 6, f = idx & 63;
            double inv = pow(10000.0, -(double)(2 * f) / 128.0);
            double ang = (double)s * inv;
            g_cos[idx] = (float)cos(ang);
            g_sin[idx] = (float)sin(ang);
        }
        return;
    }
    if (blk >= 512) {
        int i = (blk - 512) * 256 + tid;
        const float4* src;
        __half* dst;
        int j;
        if (i < 1048576) { src = (const float4*)Wq; dst = g_wq; j = i; }
        else if (i < 1572864) { src = (const float4*)Wk; dst = g_wk; j = i - 1048576; }
        else if (i < 2097152) { src = (const float4*)Wv; dst = g_wv; j = i - 1572864; }
        else { src = (const float4*)Wo; dst = g_wo; j = i - 2097152; }
        float4 v = src[j];
        __half2* d2 = (__half2*)(dst + (size_t)j * 4);
        d2[0] = __floats2half2_rn(v.x, v.y);
        d2[1] = __floats2half2_rn(v.z, v.w);
        return;
    }
    // ---- LoRA down for QKV + x conversion ----
    __shared__ float Ach[24][256];
    __shared__ float xch[8][256];
    int lane = tid & 31, w = tid >> 5;
    int m0 = blk * 8;
    float part[24];
#pragma unroll
    for (int r = 0; r < 24; r++) part[r] = 0.f;

    for (int kc = 0; kc < 8; kc++) {
        int kb = kc * 256;
#pragma unroll
        for (int i = 0; i < 6; i++) {
            int idx = i * 256 + tid;
            int r = idx >> 6, c4 = (idx & 63) << 2;
            const float* A = (r < 8) ? qA + (size_t)r * HIDDEN
                           : (r < 16) ? kA + (size_t)(r - 8) * HIDDEN
                                      : vA + (size_t)(r - 16) * HIDDEN;
            *(float4*)&Ach[r][c4] = *(const float4*)&A[kb + c4];
        }
#pragma unroll
        for (int i = 0; i < 2; i++) {
            int idx = i * 256 + tid;
            int r = idx >> 6, c4 = (idx & 63) << 2;
            float4 v = *(const float4*)&x[(size_t)(m0 + r) * HIDDEN + kb + c4];
            *(float4*)&xch[r][c4] = v;
            __half2* o = (__half2*)&g_xr[(size_t)(m0 + r) * HIDDEN + kb + c4];
            o[0] = __floats2half2_rn(v.x, v.y);
            o[1] = __floats2half2_rn(v.z, v.w);
        }
        __syncthreads();
        float xv[8];
#pragma unroll
        for (int i = 0; i < 8; i++) xv[i] = xch[w][lane + 32 * i];
#pragma unroll
        for (int r = 0; r < 24; r++) {
            float s = 0.f;
#pragma unroll
            for (int i = 0; i < 8; i++) s += xv[i] * Ach[r][lane + 32 * i];
            part[r] += s;
        }
        __syncthreads();
    }
#pragma unroll
    for (int r = 0; r < 24; r++) {
        float v = part[r];
#pragma unroll
        for (int o = 16; o > 0; o >>= 1) v += __shfl_xor_sync(0xffffffffu, v, o);
        part[r] = v;
    }
    if (lane == 0) {
        int m = m0 + w;
#pragma unroll
        for (int r = 0; r < 8; r++) {
            g_tq[m * RANK + r] = part[r];
            g_tk[m * RANK + r] = part[8 + r];
            g_tv[m * RANK + r] = part[16 + r];
        }
    }
}

// ---------------- LoRA down: O, 8 rows/block ----------------------------------
__global__ void __launch_bounds__(256) lora_down_o2(const float* __restrict__ oA) {
    __shared__ float Ach[8][256];
    __shared__ float xch[8][256];
    int tid = threadIdx.x, lane = tid & 31, w = tid >> 5;
    int m0 = blockIdx.x * 8;
    float part[8];
#pragma unroll
    for (int r = 0; r < 8; r++) part[r] = 0.f;

    for (int kc = 0; kc < 8; kc++) {
        int kb = kc * 256;
#pragma unroll
        for (int i = 0; i < 2; i++) {
            int idx = i * 256 + tid;
            int r = idx >> 6, c4 = (idx & 63) << 2;
            *(float4*)&Ach[r][c4] = *(const float4*)&oA[(size_t)r * (NQ * HD) + kb + c4];
            int m = m0 + r, b = m >> 11, s = m & 2047;
            int k = kb + c4, h = k >> 7, d = k & 127;
            const __half2* src =
                (const __half2*)&g_attn[(((size_t)(b * NQ + h)) * SEQ + s) * HD + d];
            float2 f0 = __half22float2(src[0]);
            float2 f1 = __half22float2(src[1]);
            *(float4*)&xch[r][c4] = make_float4(f0.x, f0.y, f1.x, f1.y);
        }
        __syncthreads();
        float xv[8];
#pragma unroll
        for (int i = 0; i < 8; i++) xv[i] = xch[w][lane + 32 * i];
#pragma unroll
        for (int r = 0; r < 8; r++) {
            float s = 0.f;
#pragma unroll
            for (int i = 0; i < 8; i++) s += xv[i] * Ach[r][lane + 32 * i];
            part[r] += s;
        }
        __syncthreads();
    }
#pragma unroll
    for (int r = 0; r < 8; r++) {
        float v = part[r];
#pragma unroll
        for (int o = 16; o > 0; o >>= 1) v += __shfl_xor_sync(0xffffffffu, v, o);
        part[r] = v;
    }
    if (lane == 0) {
        int m = m0 + w;
#pragma unroll
        for (int r = 0; r < 8; r++) g_to[m * RANK + r] = part[r];
    }
}

// ---------------- fp16 GEMM: persistent tiles, cp.async + ldmatrix -------------
#define GEMM_SMEM 65536

template <int IS_O>
__global__ void __launch_bounds__(256, 2) gemm6_kernel(
    const float* __restrict__ qBp, const float* __restrict__ kBp,
    const float* __restrict__ vBp, float* __restrict__ Out) {
    extern __shared__ uint32_t smw[];
    const int tid = threadIdx.x, lane = tid & 31, wid = tid >> 5;
    const int g = lane >> 2, tig = lane & 3;
    const int wm = (wid & 3) * 32, wn = (wid >> 2) * 64;
    const uint32_t smb = s2u(smw);

    // tile-independent constants
    const int fr = tid >> 1;
    const int fj0 = (tid & 1) * 2;
    const int fsw = (fr >> 1) & 3;
    const int rowAoff = (lane & 7) + ((lane >> 3) & 1) * 8;
    const int hiA = lane >> 4;
    const int swA = (rowAoff >> 1) & 3;
    const int rowBoff = (lane & 7) + ((lane >> 4) << 3);
    const int hiB = (lane >> 3) & 1;
    const int swB = (rowBoff >> 1) & 3;
    uint32_t aAddr[2], bAddr[4];
#pragma unroll
    for (int mt = 0; mt < 2; mt++)
        aAddr[mt] = smb + (uint32_t)((wm + mt * 16 + rowAoff) * 64);
#pragma unroll
    for (int p = 0; p < 4; p++)
        bAddr[p] = smb + 32768u + (uint32_t)((wn + p * 16 + rowBoff) * 64);

    const int TOT = IS_O ? 512 : 1024;
    for (int t = blockIdx.x; t < TOT; t += gridDim.x) {
        const int nb = IS_O ? (t & 15) : (t & 31);
        const int m0 = (IS_O ? (t >> 4) : (t >> 5)) * 128;

        const __half* W;
        const float *U, *T;
        int which, nrel0;
        if (IS_O) {
            which = 3; nrel0 = nb * 128;
            W = g_wo + (size_t)nrel0 * HIDDEN; U = qBp + nrel0 * RANK; T = g_to;
        } else if (nb < 16) {
            which = 0; nrel0 = nb * 128;
            W = g_wq + (size_t)nrel0 * HIDDEN; U = qBp + nrel0 * RANK; T = g_tq;
        } else if (nb < 24) {
            which = 1; nrel0 = nb * 128 - 2048;
            W = g_wk + (size_t)nrel0 * HIDDEN; U = kBp + nrel0 * RANK; T = g_tk;
        } else {
            which = 2; nrel0 = nb * 128 - 3072;
            W = g_wv + (size_t)nrel0 * HIDDEN; U = vBp + nrel0 * RANK; T = g_tv;
        }

        const __half* srcB = W + (size_t)fr * HIDDEN;
        size_t aoff;
        if (IS_O) {
            int m = m0 + fr, b = m >> 11, s = m & 2047;
            aoff = (((size_t)(b * NQ)) * SEQ + s) * HD;
        } else {
            aoff = (size_t)(m0 + fr) * HIDDEN;
        }

        auto fill = [&](int st, int kc) {
            uint32_t dA = smb + (uint32_t)st * 8192u + (uint32_t)fr * 64u;
#pragma unroll
            for (int u = 0; u < 2; u++) {
                int j = fj0 + u;
                int k = kc * 32 + j * 8;
                const char* sA;
                if (IS_O) {
                    int hh = k >> 7, dd = k & 127;
                    sA = (const char*)(g_attn + aoff + (size_t)hh * SEQ * HD + dd);
                } else {
                    sA = (const char*)(g_xr + aoff + k);
                }
                uint32_t dsw = (uint32_t)((j ^ fsw) << 4);
                CPA16(dA + dsw, sA);
                CPA16(dA + 32768u + dsw, (const char*)(srcB + k));
            }
        };

        float acc[2][8][4];
#pragma unroll
        for (int a = 0; a < 2; a++)
#pragma unroll
            for (int b2 = 0; b2 < 8; b2++)
#pragma unroll
                for (int c = 0; c < 4; c++) acc[a][b2][c] = 0.f;

        __syncthreads();   // all warps done with previous tile's smem
        fill(0, 0); CPC();
        fill(1, 1); CPC();
        fill(2, 2); CPC();

        const int NKC = HIDDEN / 32;   // 64
        for (int kc = 0; kc < NKC; kc++) {
            CPW(2);
            __syncthreads();
            if (kc + 3 < NKC) { fill((kc + 3) & 3, kc + 3); CPC(); } else { CPC(); }
            uint32_t sb = (uint32_t)((kc & 3) * 8192);
#pragma unroll
            for (int c = 0; c < 2; c++) {
                uint4 Af0, Af1;
                uint32_t ga = (uint32_t)((((2 * c + hiA) ^ swA) << 4));
                ldsm4(Af0, aAddr[0] + sb + ga);
                ldsm4(Af1, aAddr[1] + sb + ga);
                uint32_t gb = (uint32_t)((((2 * c + hiB) ^ swB) << 4));
#pragma unroll
                for (int p = 0; p < 4; p++) {
                    uint4 Bf;
                    ldsm4(Bf, bAddr[p] + sb + gb);
                    mma16(acc[0][2 * p],     Af0, Bf.x, Bf.y);
                    mma16(acc[0][2 * p + 1], Af0, Bf.z, Bf.w);
                    mma16(acc[1][2 * p],     Af1, Bf.x, Bf.y);
                    mma16(acc[1][2 * p + 1], Af1, Bf.z, Bf.w);
                }
            }
        }

        // LoRA rank-8 tail
        __syncthreads();
        {
            int r = tid & 127;
            const float* src;
            float sc;
            uint32_t base;
            if (tid < 128) { src = T + (size_t)(m0 + r) * RANK; sc = 1.f; base = 0; }
            else           { src = U + (size_t)r * RANK; sc = LORA_SC; base = 8192; }
            __half2 h0 = __floats2half2_rn(src[0] * sc, src[1] * sc);
            __half2 h1 = __floats2half2_rn(src[2] * sc, src[3] * sc);
            __half2 h2 = __floats2half2_rn(src[4] * sc, src[5] * sc);
            __half2 h3 = __floats2half2_rn(src[6] * sc, src[7] * sc);
            int sw = (r >> 1) & 3;
            uint32_t w0 = base + r * 16 + ((0 ^ sw) << 2);
            uint32_t w1 = base + r * 16 + ((1 ^ sw) << 2);
            smw[w0 + 0] = h2u(h0); smw[w0 + 1] = h2u(h1);
            smw[w0 + 2] = h2u(h2); smw[w0 + 3] = h2u(h3);
            smw[w1 + 0] = 0; smw[w1 + 1] = 0; smw[w1 + 2] = 0; smw[w1 + 3] = 0;
        }
        __syncthreads();
        {
            uint4 Af0, Af1;
            uint32_t ga = (uint32_t)(((hiA ^ swA) << 4));
            ldsm4(Af0, aAddr[0] + ga);
            ldsm4(Af1, aAddr[1] + ga);
            uint32_t gb = (uint32_t)(((hiB ^ swB) << 4));
#pragma unroll
            for (int p = 0; p < 4; p++) {
                uint4 Bf;
                ldsm4(Bf, bAddr[p] + gb);
                mma16(acc[0][2 * p],     Af0, Bf.x, Bf.y);
                mma16(acc[0][2 * p + 1], Af0, Bf.z, Bf.w);
                mma16(acc[1][2 * p],     Af1, Bf.x, Bf.y);
                mma16(acc[1][2 * p + 1], Af1, Bf.z, Bf.w);
            }
        }

        // epilogue
#pragma unroll
        for (int mt = 0; mt < 2; mt++) {
#pragma unroll
            for (int rr = 0; rr < 2; rr++) {
                int m = m0 + wm + mt * 16 + g + rr * 8;
                int s = m & 2047, b = m >> 11;
#pragma unroll
                for (int ni = 0; ni < 8; ni++) {
                    int nrel = nrel0 + wn + ni * 8 + 2 * tig;
                    float v0 = acc[mt][ni][rr * 2 + 0];
                    float v1 = acc[mt][ni][rr * 2 + 1];
                    int d = nrel & 127;
                    if (which <= 1) {
                        int f = d >> 1;
                        float c = g_cos[s * 64 + f], sn = g_sin[s * 64 + f];
                        float t0 = v0 * c - v1 * sn;
                        v1 = v0 * sn + v1 * c;
                        v0 = t0;
                    }
                    if (which == 3) {
                        *(float2*)&Out[(size_t)m * HIDDEN + nrel] = make_float2(v0, v1);
                    } else if (which == 0) {
                        *(__half2*)&g_q[(((size_t)(b * NQ + (nrel >> 7))) * SEQ + s) * HD + d] =
                            __floats2half2_rn(v0 * (SM_SCALE * LOG2E), v1 * (SM_SCALE * LOG2E));
                    } else if (which == 1) {
                        *(__half2*)&g_k[(((size_t)(b * NKV + (nrel >> 7))) * SEQ + s) * HD + d] =
                            __floats2half2_rn(v0, v1);
                    } else {
                        __half* vb = g_vT + (((size_t)(b * NKV + (nrel >> 7))) * HD + d) * SEQ;
                        vb[s] = __float2half_rn(v0);
                        vb[SEQ + s] = __float2half_rn(v1);
                    }
                }
            }
        }
    }
}

// ---------------- fp16 flash attention (exp2-domain softmax, R12 config) -------
#define FL_SMEM 114688

__global__ void __launch_bounds__(256, 2) flash_kernel() {
    extern __shared__ uint32_t sm[];
    const int tid = threadIdx.x, lane = tid & 31, wid = tid >> 5;
    const int g = lane >> 2, tig = lane & 3;
    int qb = (gridDim.x - 1) - blockIdx.x;
    int bh = blockIdx.y;
    int b = bh >> 4, h = bh & 15, kvh = h >> 1;
    const __half* Qb = g_q + ((size_t)(b * NQ + h)) * SEQ * HD;
    const __half* Kb = g_k + ((size_t)(b * NKV + kvh)) * SEQ * HD;
    const __half* Vb = g_vT + ((size_t)(b * NKV + kvh)) * HD * SEQ;
    int q0 = qb * 128, rb0 = wid * 16;
    const uint32_t smb = s2u(sm);

    const int rowAoff = (lane & 7) + ((lane >> 3) & 1) * 8;
    const int hiA = lane >> 4;
    const int swA = rowAoff & 7;
    const int rowBoff = (lane & 7) + ((lane >> 4) << 3);
    const int hiB = (lane >> 3) & 1;
    const int swB = rowBoff & 7;

    const uint32_t qA_base = smb + (uint32_t)((rb0 + rowAoff) * 256);
    const uint32_t pA_base = smb + 98304u + (uint32_t)((rb0 + rowAoff) * 128);
    uint32_t kB_base[4], vB_base[8];
#pragma unroll
    for (int p = 0; p < 4; p++)
        kB_base[p] = smb + 32768u + (uint32_t)((p * 16 + rowBoff) * 256);
#pragma unroll
    for (int p = 0; p < 8; p++)
        vB_base[p] = smb + 65536u + (uint32_t)((p * 16 + rowBoff) * 128);

#pragma unroll
    for (int i = 0; i < 8; i++) {
        int gid = i * 256 + tid;
        int r = gid >> 4, j = gid & 15;
        CPA16(smb + (uint32_t)(r * 256 + ((j ^ (r & 7)) << 4)),
              (const char*)(Qb + (size_t)(q0 + r) * HD + j * 8));
    }
    CPC();
    auto fillKV = [&](int kt, int st) {
        int k0 = kt * 64;
        uint32_t kst = smb + 32768u + (uint32_t)st * 16384u;
        uint32_t vst = smb + 65536u + (uint32_t)st * 16384u;
#pragma unroll
        for (int i = 0; i < 4; i++) {
            int gid = i * 256 + tid;
            int r = gid >> 4, j = gid & 15;
            CPA16(kst + (uint32_t)(r * 256 + ((j ^ (r & 7)) << 4)),
                  (const char*)(Kb + (size_t)(k0 + r) * HD + j * 8));
        }
#pragma unroll
        for (int i = 0; i < 4; i++) {
            int gid = i * 256 + tid;
            int rv = gid >> 3, jv = gid & 7;
            CPA16(vst + (uint32_t)(rv * 128 + ((jv ^ (rv & 7)) << 4)),
                  (const char*)(Vb + (size_t)rv * SEQ + k0 + jv * 8));
        }
    };
    fillKV(0, 0);
    CPC();

    float O[16][4];
#pragma unroll
    for (int i = 0; i < 16; i++)
#pragma unroll
        for (int j = 0; j < 4; j++) O[i][j] = 0.f;
    float mrow[2] = {-1e30f, -1e30f}, lrow[2] = {0.f, 0.f};

    int ktmax = 2 * qb + 1;
    for (int kt = 0; kt <= ktmax; kt++) {
        __syncthreads();
        if (kt < ktmax) { fillKV(kt + 1, (kt + 1) & 1); CPC(); } else { CPC(); }
        CPW(1);
        __syncthreads();
        uint32_t ksb = (kt & 1) ? 16384u : 0u;
        int k0 = kt * 64;

        float sacc[8][4];
#pragma unroll
        for (int i = 0; i < 8; i++)
#pragma unroll
            for (int j = 0; j < 4; j++) sacc[i][j] = 0.f;
#pragma unroll
        for (int c = 0; c < 8; c++) {
            uint4 Qf;
            ldsm4(Qf, qA_base + (uint32_t)((((2 * c + hiA) ^ swA) << 4)));
            uint32_t gb = (uint32_t)((((2 * c + hiB) ^ swB) << 4));
#pragma unroll
            for (int p = 0; p < 4; p++) {
                uint4 Kf;
                ldsm4(Kf, kB_base[p] + ksb + gb);
                mma16(sacc[2 * p],     Qf, Kf.x, Kf.y);
                mma16(sacc[2 * p + 1], Qf, Kf.z, Kf.w);
            }
        }
        if (kt >= 2 * qb) {
#pragma unroll
            for (int ni = 0; ni < 8; ni++)
#pragma unroll
                for (int j = 0; j < 4; j++) {
                    int col = k0 + ni * 8 + 2 * tig + (j & 1);
                    int row = q0 + rb0 + g + ((j >> 1) << 3);
                    if (col > row) sacc[ni][j] = -1e30f;
                }
        }
#pragma unroll
        for (int rr = 0; rr < 2; rr++) {
            float mx = -1e30f;
#pragma unroll
            for (int ni = 0; ni < 8; ni++)
                mx = fmaxf(mx, fmaxf(sacc[ni][rr * 2], sacc[ni][rr * 2 + 1]));
            mx = fmaxf(mx, __shfl_xor_sync(0xffffffffu, mx, 1));
            mx = fmaxf(mx, __shfl_xor_sync(0xffffffffu, mx, 2));
            float mnew = fmaxf(mrow[rr], mx);
            float corr = exp2f(mrow[rr] - mnew);
            float rs = 0.f;
#pragma unroll
            for (int ni = 0; ni < 8; ni++) {
                float p0 = exp2f(sacc[ni][rr * 2] - mnew);
                float p1 = exp2f(sacc[ni][rr * 2 + 1] - mnew);
                sacc[ni][rr * 2] = p0;
                sacc[ni][rr * 2 + 1] = p1;
                rs += p0 + p1;
            }
            rs += __shfl_xor_sync(0xffffffffu, rs, 1);
            rs += __shfl_xor_sync(0xffffffffu, rs, 2);
            lrow[rr] = lrow[rr] * corr + rs;
            mrow[rr] = mnew;
#pragma unroll
            for (int ni = 0; ni < 16; ni++) {
                O[ni][rr * 2] *= corr;
                O[ni][rr * 2 + 1] *= corr;
            }
            int prow = rb0 + g + rr * 8;
            int psw = prow & 7;
            char* Pr = (char*)sm + 98304 + prow * 128;
#pragma unroll
            for (int ni = 0; ni < 8; ni++) {
                *(__half2*)(Pr + ((ni ^ psw) << 4) + 4 * tig) =
                    __floats2half2_rn(sacc[ni][rr * 2], sacc[ni][rr * 2 + 1]);
            }
        }
        __syncwarp();
#pragma unroll
        for (int c = 0; c < 4; c++) {
            uint4 Pf;
            ldsm4(Pf, pA_base + (uint32_t)((((2 * c + hiA) ^ swA) << 4)));
            uint32_t gb = (uint32_t)((((2 * c + hiB) ^ swB) << 4));
#pragma unroll
            for (int p = 0; p < 8; p++) {
                uint4 Vf;
                ldsm4(Vf, vB_base[p] + ksb + gb);
                mma16(O[2 * p],     Pf, Vf.x, Vf.y);
                mma16(O[2 * p + 1], Pf, Vf.z, Vf.w);
            }
        }
    }

    __half* Ob = g_attn + ((size_t)(b * NQ + h)) * SEQ * HD;
#pragma unroll
    for (int rr = 0; rr < 2; rr++) {
        float inv = 1.f / lrow[rr];
        int r = q0 + rb0 + g + rr * 8;
#pragma unroll
        for (int ni = 0; ni < 16; ni++) {
            *(__half2*)&Ob[(size_t)r * HD + ni * 8 + 2 * tig] =
                __floats2half2_rn(O[ni][rr * 2] * inv, O[ni][rr * 2 + 1] * inv);
        }
    }
}

// ---------------- launch ------------------------------------------------------
extern "C" void kernel_launch(void* const* d_in, const int* in_sizes, int n_in,
                              void* d_out, int out_size) {
    const float* x  = (const float*)d_in[0];
    const float* Wq = (const float*)d_in[1];
    const float* Wk = (const float*)d_in[2];
    const float* Wv = (const float*)d_in[3];
    const float* Wo = (const float*)d_in[4];
    const float* qA = (const float*)d_in[5];
    const float* qB = (const float*)d_in[6];
    const float* kA = (const float*)d_in[7];
    const float* kB = (const float*)d_in[8];
    const float* vA = (const float*)d_in[9];
    const float* vB = (const float*)d_in[10];
    const float* oA = (const float*)d_in[11];
    const float* oB = (const float*)d_in[12];
    float* out = (float*)d_out;

    cudaFuncSetAttribute(gemm6_kernel<0>, cudaFuncAttributeMaxDynamicSharedMemorySize, GEMM_SMEM);
    cudaFuncSetAttribute(gemm6_kernel<1>, cudaFuncAttributeMaxDynamicSharedMemorySize, GEMM_SMEM);
    cudaFuncSetAttribute(flash_kernel, cudaFuncAttributeMaxDynamicSharedMemorySize, FL_SMEM);

    prep_kernel<<<13312, 256>>>(x, qA, kA, vA, Wq, Wk, Wv, Wo);

    gemm6_kernel<0><<<296, 256, GEMM_SMEM>>>(qB, kB, vB, nullptr);

    flash_kernel<<<dim3(SEQ / 128, BATCH * NQ), 256, FL_SMEM>>>();

    lora_down_o2<<<512, 256>>>(oA);
    gemm6_kernel<1><<<296, 256, GEMM_SMEM>>>(oB, nullptr, nullptr, out);
}

// round 15
// speedup vs baseline: 1.5395x; 1.0117x over previous
#include <cuda_runtime.h>
#include <cuda_fp16.h>
#include <math.h>
#include <stdint.h>

#define HIDDEN 2048
#define NQ 16
#define NKV 8
#define HD 128
#define SEQ 2048
#define BATCH 2
#define MROWS 4096
#define RANK 8
#define LORA_SC 2.0f
#define SM_SCALE 0.08838834764831845f
#define LOG2E 1.4426950408889634f

// ---------------- scratch (fp16 staged tensors) --------------------------------
__device__ __half g_q[8388608];      // [B][NQ][S][D]  (pre-scaled by SM_SCALE*LOG2E)
__device__ __half g_k[4194304];      // [B][NKV][S][D]
__device__ __half g_vT[4194304];     // [B][NKV][D][S]
__device__ __half g_attn[8388608];   // [B][NQ][S][D]
__device__ __half g_xr[8388608];     // fp16 x
__device__ __half g_wq[4194304];
__device__ __half g_wk[2097152];
__device__ __half g_wv[2097152];
__device__ __half g_wo[4194304];
__device__ float g_tq[MROWS * RANK];
__device__ float g_tk[MROWS * RANK];
__device__ float g_tv[MROWS * RANK];
__device__ float g_to[MROWS * RANK];
__device__ float g_cos[SEQ * 64];
__device__ float g_sin[SEQ * 64];

// ---------------- helpers -----------------------------------------------------
__device__ __forceinline__ void mma16(float* c, const uint4& a, uint32_t b0, uint32_t b1) {
    asm volatile(
        "mma.sync.aligned.m16n8k16.row.col.f32.f16.f16.f32 "
        "{%0,%1,%2,%3}, {%4,%5,%6,%7}, {%8,%9}, {%0,%1,%2,%3};\n"
        : "+f"(c[0]), "+f"(c[1]), "+f"(c[2]), "+f"(c[3])
        : "r"(a.x), "r"(a.y), "r"(a.z), "r"(a.w), "r"(b0), "r"(b1));
}

__device__ __forceinline__ uint32_t s2u(const void* p) {
    uint32_t r;
    asm("{ .reg .u64 t; cvta.to.shared.u64 t, %1; cvt.u32.u64 %0, t; }"
        : "=r"(r) : "l"(p));
    return r;
}

#define CPA16(dst, src) \
    asm volatile("cp.async.cg.shared.global [%0], [%1], 16;\n" ::"r"(dst), "l"(src))
#define CPC() asm volatile("cp.async.commit_group;\n")
#define CPW(n) asm volatile("cp.async.wait_group %0;\n" ::"n"(n))

__device__ __forceinline__ void ldsm4(uint4& d, uint32_t a) {
    asm volatile("ldmatrix.sync.aligned.m8n8.x4.shared.b16 {%0,%1,%2,%3}, [%4];\n"
                 : "=r"(d.x), "=r"(d.y), "=r"(d.z), "=r"(d.w)
                 : "r"(a));
}

__device__ __forceinline__ uint32_t h2u(__half2 h) { return *(uint32_t*)&h; }

// ---------------- merged prologue ----------------------------------------------
// blocks [0,512): LoRA down-projection for Q/K/V + x fp16 conversion (8 rows/blk)
// blocks [512, 12800): weight fp16 conversion (3145728 float4 tasks)
// blocks [12800, 13312): rope table (131072 entries)
__global__ void __launch_bounds__(256) prep_kernel(const float* __restrict__ x,
                                                   const float* __restrict__ qA,
                                                   const float* __restrict__ kA,
                                                   const float* __restrict__ vA,
                                                   const float* __restrict__ Wq,
                                                   const float* __restrict__ Wk,
                                                   const float* __restrict__ Wv,
                                                   const float* __restrict__ Wo) {
    int blk = blockIdx.x;
    int tid = threadIdx.x;
    if (blk >= 12800) {
        int idx = (blk - 12800) * 256 + tid;
        if (idx < SEQ * 64) {
            int s = idx >> 6, f = idx & 63;
            double inv = pow(10000.0, -(double)(2 * f) / 128.0);
            double ang = (double)s * inv;
            g_cos[idx] = (float)cos(ang);
            g_sin[idx] = (float)sin(ang);
        }
        return;
    }
    if (blk >= 512) {
        int i = (blk - 512) * 256 + tid;
        const float4* src;
        __half* dst;
        int j;
        if (i < 1048576) { src = (const float4*)Wq; dst = g_wq; j = i; }
        else if (i < 1572864) { src = (const float4*)Wk; dst = g_wk; j = i - 1048576; }
        else if (i < 2097152) { src = (const float4*)Wv; dst = g_wv; j = i - 1572864; }
        else { src = (const float4*)Wo; dst = g_wo; j = i - 2097152; }
        float4 v = src[j];
        __half2* d2 = (__half2*)(dst + (size_t)j * 4);
        d2[0] = __floats2half2_rn(v.x, v.y);
        d2[1] = __floats2half2_rn(v.z, v.w);
        return;
    }
    // ---- LoRA down for QKV + x conversion ----
    __shared__ float Ach[24][256];
    __shared__ float xch[8][256];
    int lane = tid & 31, w = tid >> 5;
    int m0 = blk * 8;
    float part[24];
#pragma unroll
    for (int r = 0; r < 24; r++) part[r] = 0.f;

    for (int kc = 0; kc < 8; kc++) {
        int kb = kc * 256;
#pragma unroll
        for (int i = 0; i < 6; i++) {
            int idx = i * 256 + tid;
            int r = idx >> 6, c4 = (idx & 63) << 2;
            const float* A = (r < 8) ? qA + (size_t)r * HIDDEN
                           : (r < 16) ? kA + (size_t)(r - 8) * HIDDEN
                                      : vA + (size_t)(r - 16) * HIDDEN;
            *(float4*)&Ach[r][c4] = *(const float4*)&A[kb + c4];
        }
#pragma unroll
        for (int i = 0; i < 2; i++) {
            int idx = i * 256 + tid;
            int r = idx >> 6, c4 = (idx & 63) << 2;
            float4 v = *(const float4*)&x[(size_t)(m0 + r) * HIDDEN + kb + c4];
            *(float4*)&xch[r][c4] = v;
            __half2* o = (__half2*)&g_xr[(size_t)(m0 + r) * HIDDEN + kb + c4];
            o[0] = __floats2half2_rn(v.x, v.y);
            o[1] = __floats2half2_rn(v.z, v.w);
        }
        __syncthreads();
        float xv[8];
#pragma unroll
        for (int i = 0; i < 8; i++) xv[i] = xch[w][lane + 32 * i];
#pragma unroll
        for (int r = 0; r < 24; r++) {
            float s = 0.f;
#pragma unroll
            for (int i = 0; i < 8; i++) s += xv[i] * Ach[r][lane + 32 * i];
            part[r] += s;
        }
        __syncthreads();
    }
#pragma unroll
    for (int r = 0; r < 24; r++) {
        float v = part[r];
#pragma unroll
        for (int o = 16; o > 0; o >>= 1) v += __shfl_xor_sync(0xffffffffu, v, o);
        part[r] = v;
    }
    if (lane == 0) {
        int m = m0 + w;
#pragma unroll
        for (int r = 0; r < 8; r++) {
            g_tq[m * RANK + r] = part[r];
            g_tk[m * RANK + r] = part[8 + r];
            g_tv[m * RANK + r] = part[16 + r];
        }
    }
}

// ---------------- LoRA down: O, 8 rows/block ----------------------------------
__global__ void __launch_bounds__(256) lora_down_o2(const float* __restrict__ oA) {
    __shared__ float Ach[8][256];
    __shared__ float xch[8][256];
    int tid = threadIdx.x, lane = tid & 31, w = tid >> 5;
    int m0 = blockIdx.x * 8;
    float part[8];
#pragma unroll
    for (int r = 0; r < 8; r++) part[r] = 0.f;

    for (int kc = 0; kc < 8; kc++) {
        int kb = kc * 256;
#pragma unroll
        for (int i = 0; i < 2; i++) {
            int idx = i * 256 + tid;
            int r = idx >> 6, c4 = (idx & 63) << 2;
            *(float4*)&Ach[r][c4] = *(const float4*)&oA[(size_t)r * (NQ * HD) + kb + c4];
            int m = m0 + r, b = m >> 11, s = m & 2047;
            int k = kb + c4, h = k >> 7, d = k & 127;
            const __half2* src =
                (const __half2*)&g_attn[(((size_t)(b * NQ + h)) * SEQ + s) * HD + d];
            float2 f0 = __half22float2(src[0]);
            float2 f1 = __half22float2(src[1]);
            *(float4*)&xch[r][c4] = make_float4(f0.x, f0.y, f1.x, f1.y);
        }
        __syncthreads();
        float xv[8];
#pragma unroll
        for (int i = 0; i < 8; i++) xv[i] = xch[w][lane + 32 * i];
#pragma unroll
        for (int r = 0; r < 8; r++) {
            float s = 0.f;
#pragma unroll
            for (int i = 0; i < 8; i++) s += xv[i] * Ach[r][lane + 32 * i];
            part[r] += s;
        }
        __syncthreads();
    }
#pragma unroll
    for (int r = 0; r < 8; r++) {
        float v = part[r];
#pragma unroll
        for (int o = 16; o > 0; o >>= 1) v += __shfl_xor_sync(0xffffffffu, v, o);
        part[r] = v;
    }
    if (lane == 0) {
        int m = m0 + w;
#pragma unroll
        for (int r = 0; r < 8; r++) g_to[m * RANK + r] = part[r];
    }
}

// ---------------- fp16 GEMM: cp.async + ldmatrix + m16n8k16 (R7 config) --------
#define GEMM_SMEM 65536

template <int IS_O>
__global__ void __launch_bounds__(256, 2) gemm6_kernel(
    const float* __restrict__ qBp, const float* __restrict__ kBp,
    const float* __restrict__ vBp, float* __restrict__ Out) {
    extern __shared__ uint32_t smw[];
    const int tid = threadIdx.x, lane = tid & 31, wid = tid >> 5;
    const int g = lane >> 2, tig = lane & 3;
    const int wm = (wid & 3) * 32, wn = (wid >> 2) * 64;
    const int m0 = blockIdx.y * 128;
    const int nb = blockIdx.x;

    const __half* W;
    const float *U, *T;
    int which, nrel0;
    if (IS_O) {
        which = 3; nrel0 = nb * 128;
        W = g_wo + (size_t)nrel0 * HIDDEN; U = qBp + nrel0 * RANK; T = g_to;
    } else if (nb < 16) {
        which = 0; nrel0 = nb * 128;
        W = g_wq + (size_t)nrel0 * HIDDEN; U = qBp + nrel0 * RANK; T = g_tq;
    } else if (nb < 24) {
        which = 1; nrel0 = nb * 128 - 2048;
        W = g_wk + (size_t)nrel0 * HIDDEN; U = kBp + nrel0 * RANK; T = g_tk;
    } else {
        which = 2; nrel0 = nb * 128 - 3072;
        W = g_wv + (size_t)nrel0 * HIDDEN; U = vBp + nrel0 * RANK; T = g_tv;
    }

    const uint32_t smb = s2u(smw);

    const int fr = tid >> 1;
    const int fj0 = (tid & 1) * 2;
    const int fsw = (fr >> 1) & 3;
    const __half* srcB = W + (size_t)fr * HIDDEN;
    size_t aoff;
    if (IS_O) {
        int m = m0 + fr, b = m >> 11, s = m & 2047;
        aoff = (((size_t)(b * NQ)) * SEQ + s) * HD;
    } else {
        aoff = (size_t)(m0 + fr) * HIDDEN;
    }

    auto fill = [&](int st, int kc) {
        uint32_t dA = smb + (uint32_t)st * 8192u + (uint32_t)fr * 64u;
#pragma unroll
        for (int u = 0; u < 2; u++) {
            int j = fj0 + u;
            int k = kc * 32 + j * 8;
            const char* sA;
            if (IS_O) {
                int hh = k >> 7, dd = k & 127;
                sA = (const char*)(g_attn + aoff + (size_t)hh * SEQ * HD + dd);
            } else {
                sA = (const char*)(g_xr + aoff + k);
            }
            uint32_t dsw = (uint32_t)((j ^ fsw) << 4);
            CPA16(dA + dsw, sA);
            CPA16(dA + 32768u + dsw, (const char*)(srcB + k));
        }
    };

    const int rowAoff = (lane & 7) + ((lane >> 3) & 1) * 8;
    const int hiA = lane >> 4;
    const int swA = (rowAoff >> 1) & 3;
    const int rowBoff = (lane & 7) + ((lane >> 4) << 3);
    const int hiB = (lane >> 3) & 1;
    const int swB = (rowBoff >> 1) & 3;
    uint32_t aAddr[2], bAddr[4];
#pragma unroll
    for (int mt = 0; mt < 2; mt++)
        aAddr[mt] = smb + (uint32_t)((wm + mt * 16 + rowAoff) * 64);
#pragma unroll
    for (int p = 0; p < 4; p++)
        bAddr[p] = smb + 32768u + (uint32_t)((wn + p * 16 + rowBoff) * 64);

    float acc[2][8][4];
#pragma unroll
    for (int a = 0; a < 2; a++)
#pragma unroll
        for (int b2 = 0; b2 < 8; b2++)
#pragma unroll
            for (int c = 0; c < 4; c++) acc[a][b2][c] = 0.f;

    fill(0, 0); CPC();
    fill(1, 1); CPC();
    fill(2, 2); CPC();

    const int NKC = HIDDEN / 32;   // 64
    for (int kc = 0; kc < NKC; kc++) {
        CPW(2);
        __syncthreads();
        if (kc + 3 < NKC) { fill((kc + 3) & 3, kc + 3); CPC(); } else { CPC(); }
        uint32_t sb = (uint32_t)((kc & 3) * 8192);
#pragma unroll
        for (int c = 0; c < 2; c++) {
            uint4 Af0, Af1;
            uint32_t ga = (uint32_t)((((2 * c + hiA) ^ swA) << 4));
            ldsm4(Af0, aAddr[0] + sb + ga);
            ldsm4(Af1, aAddr[1] + sb + ga);
            uint32_t gb = (uint32_t)((((2 * c + hiB) ^ swB) << 4));
#pragma unroll
            for (int p = 0; p < 4; p++) {
                uint4 Bf;
                ldsm4(Bf, bAddr[p] + sb + gb);
                mma16(acc[0][2 * p],     Af0, Bf.x, Bf.y);
                mma16(acc[0][2 * p + 1], Af0, Bf.z, Bf.w);
                mma16(acc[1][2 * p],     Af1, Bf.x, Bf.y);
                mma16(acc[1][2 * p + 1], Af1, Bf.z, Bf.w);
            }
        }
    }

    // LoRA rank-8 tail
    __syncthreads();
    {
        int r = tid & 127;
        const float* src;
        float sc;
        uint32_t base;
        if (tid < 128) { src = T + (size_t)(m0 + r) * RANK; sc = 1.f; base = 0; }
        else           { src = U + (size_t)r * RANK; sc = LORA_SC; base = 8192; }
        __half2 h0 = __floats2half2_rn(src[0] * sc, src[1] * sc);
        __half2 h1 = __floats2half2_rn(src[2] * sc, src[3] * sc);
        __half2 h2 = __floats2half2_rn(src[4] * sc, src[5] * sc);
        __half2 h3 = __floats2half2_rn(src[6] * sc, src[7] * sc);
        int sw = (r >> 1) & 3;
        uint32_t w0 = base + r * 16 + ((0 ^ sw) << 2);
        uint32_t w1 = base + r * 16 + ((1 ^ sw) << 2);
        smw[w0 + 0] = h2u(h0); smw[w0 + 1] = h2u(h1);
        smw[w0 + 2] = h2u(h2); smw[w0 + 3] = h2u(h3);
        smw[w1 + 0] = 0; smw[w1 + 1] = 0; smw[w1 + 2] = 0; smw[w1 + 3] = 0;
    }
    __syncthreads();
    {
        uint4 Af0, Af1;
        uint32_t ga = (uint32_t)(((hiA ^ swA) << 4));
        ldsm4(Af0, aAddr[0] + ga);
        ldsm4(Af1, aAddr[1] + ga);
        uint32_t gb = (uint32_t)(((hiB ^ swB) << 4));
#pragma unroll
        for (int p = 0; p < 4; p++) {
            uint4 Bf;
            ldsm4(Bf, bAddr[p] + gb);
            mma16(acc[0][2 * p],     Af0, Bf.x, Bf.y);
            mma16(acc[0][2 * p + 1], Af0, Bf.z, Bf.w);
            mma16(acc[1][2 * p],     Af1, Bf.x, Bf.y);
            mma16(acc[1][2 * p + 1], Af1, Bf.z, Bf.w);
        }
    }

    // epilogue
#pragma unroll
    for (int mt = 0; mt < 2; mt++) {
#pragma unroll
        for (int rr = 0; rr < 2; rr++) {
            int m = m0 + wm + mt * 16 + g + rr * 8;
            int s = m & 2047, b = m >> 11;
#pragma unroll
            for (int ni = 0; ni < 8; ni++) {
                int nrel = nrel0 + wn + ni * 8 + 2 * tig;
                float v0 = acc[mt][ni][rr * 2 + 0];
                float v1 = acc[mt][ni][rr * 2 + 1];
                int d = nrel & 127;
                if (which <= 1) {
                    int f = d >> 1;
                    float c = g_cos[s * 64 + f], sn = g_sin[s * 64 + f];
                    float t0 = v0 * c - v1 * sn;
                    v1 = v0 * sn + v1 * c;
                    v0 = t0;
                }
                if (which == 3) {
                    *(float2*)&Out[(size_t)m * HIDDEN + nrel] = make_float2(v0, v1);
                } else if (which == 0) {
                    *(__half2*)&g_q[(((size_t)(b * NQ + (nrel >> 7))) * SEQ + s) * HD + d] =
                        __floats2half2_rn(v0 * (SM_SCALE * LOG2E), v1 * (SM_SCALE * LOG2E));
                } else if (which == 1) {
                    *(__half2*)&g_k[(((size_t)(b * NKV + (nrel >> 7))) * SEQ + s) * HD + d] =
                        __floats2half2_rn(v0, v1);
                } else {
                    __half* vb = g_vT + (((size_t)(b * NKV + (nrel >> 7))) * HD + d) * SEQ;
                    vb[s] = __float2half_rn(v0);
                    vb[SEQ + s] = __float2half_rn(v1);
                }
            }
        }
    }
}

// ---------------- fp16 flash attention (exp2-domain softmax) -------------------
#define FL_SMEM 114688

__global__ void __launch_bounds__(256, 2) flash_kernel() {
    extern __shared__ uint32_t sm[];
    const int tid = threadIdx.x, lane = tid & 31, wid = tid >> 5;
    const int g = lane >> 2, tig = lane & 3;
    int qb = (gridDim.x - 1) - blockIdx.x;
    int bh = blockIdx.y;
    int b = bh >> 4, h = bh & 15, kvh = h >> 1;
    const __half* Qb = g_q + ((size_t)(b * NQ + h)) * SEQ * HD;
    const __half* Kb = g_k + ((size_t)(b * NKV + kvh)) * SEQ * HD;
    const __half* Vb = g_vT + ((size_t)(b * NKV + kvh)) * HD * SEQ;
    int q0 = qb * 128, rb0 = wid * 16;
    const uint32_t smb = s2u(sm);

    const int rowAoff = (lane & 7) + ((lane >> 3) & 1) * 8;
    const int hiA = lane >> 4;
    const int swA = rowAoff & 7;
    const int rowBoff = (lane & 7) + ((lane >> 4) << 3);
    const int hiB = (lane >> 3) & 1;
    const int swB = rowBoff & 7;

    const uint32_t qA_base = smb + (uint32_t)((rb0 + rowAoff) * 256);
    const uint32_t pA_base = smb + 98304u + (uint32_t)((rb0 + rowAoff) * 128);
    uint32_t kB_base[4], vB_base[8];
#pragma unroll
    for (int p = 0; p < 4; p++)
        kB_base[p] = smb + 32768u + (uint32_t)((p * 16 + rowBoff) * 256);
#pragma unroll
    for (int p = 0; p < 8; p++)
        vB_base[p] = smb + 65536u + (uint32_t)((p * 16 + rowBoff) * 128);

#pragma unroll
    for (int i = 0; i < 8; i++) {
        int gid = i * 256 + tid;
        int r = gid >> 4, j = gid & 15;
        CPA16(smb + (uint32_t)(r * 256 + ((j ^ (r & 7)) << 4)),
              (const char*)(Qb + (size_t)(q0 + r) * HD + j * 8));
    }
    CPC();
    auto fillKV = [&](int kt, int st) {
        int k0 = kt * 64;
        uint32_t kst = smb + 32768u + (uint32_t)st * 16384u;
        uint32_t vst = smb + 65536u + (uint32_t)st * 16384u;
#pragma unroll
        for (int i = 0; i < 4; i++) {
            int gid = i * 256 + tid;
            int r = gid >> 4, j = gid & 15;
            CPA16(kst + (uint32_t)(r * 256 + ((j ^ (r & 7)) << 4)),
                  (const char*)(Kb + (size_t)(k0 + r) * HD + j * 8));
        }
#pragma unroll
        for (int i = 0; i < 4; i++) {
            int gid = i * 256 + tid;
            int rv = gid >> 3, jv = gid & 7;
            CPA16(vst + (uint32_t)(rv * 128 + ((jv ^ (rv & 7)) << 4)),
                  (const char*)(Vb + (size_t)rv * SEQ + k0 + jv * 8));
        }
    };
    fillKV(0, 0);
    CPC();

    float O[16][4];
#pragma unroll
    for (int i = 0; i < 16; i++)
#pragma unroll
        for (int j = 0; j < 4; j++) O[i][j] = 0.f;
    float mrow[2] = {-1e30f, -1e30f}, lrow[2] = {0.f, 0.f};

    int ktmax = 2 * qb + 1;
    for (int kt = 0; kt <= ktmax; kt++) {
        __syncthreads();
        if (kt < ktmax) { fillKV(kt + 1, (kt + 1) & 1); CPC(); } else { CPC(); }
        CPW(1);
        __syncthreads();
        uint32_t ksb = (kt & 1) ? 16384u : 0u;
        int k0 = kt * 64;

        float sacc[8][4];
#pragma unroll
        for (int i = 0; i < 8; i++)
#pragma unroll
            for (int j = 0; j < 4; j++) sacc[i][j] = 0.f;
#pragma unroll
        for (int c = 0; c < 8; c++) {
            uint4 Qf;
            ldsm4(Qf, qA_base + (uint32_t)((((2 * c + hiA) ^ swA) << 4)));
            uint32_t gb = (uint32_t)((((2 * c + hiB) ^ swB) << 4));
#pragma unroll
            for (int p = 0; p < 4; p++) {
                uint4 Kf;
                ldsm4(Kf, kB_base[p] + ksb + gb);
                mma16(sacc[2 * p],     Qf, Kf.x, Kf.y);
                mma16(sacc[2 * p + 1], Qf, Kf.z, Kf.w);
            }
        }
        if (kt >= 2 * qb) {
#pragma unroll
            for (int ni = 0; ni < 8; ni++)
#pragma unroll
                for (int j = 0; j < 4; j++) {
                    int col = k0 + ni * 8 + 2 * tig + (j & 1);
                    int row = q0 + rb0 + g + ((j >> 1) << 3);
                    if (col > row) sacc[ni][j] = -1e30f;
                }
        }
#pragma unroll
        for (int rr = 0; rr < 2; rr++) {
            float mx = -1e30f;
#pragma unroll
            for (int ni = 0; ni < 8; ni++)
                mx = fmaxf(mx, fmaxf(sacc[ni][rr * 2], sacc[ni][rr * 2 + 1]));
            mx = fmaxf(mx, __shfl_xor_sync(0xffffffffu, mx, 1));
            mx = fmaxf(mx, __shfl_xor_sync(0xffffffffu, mx, 2));
            float mnew = fmaxf(mrow[rr], mx);
            float corr = exp2f(mrow[rr] - mnew);
            float rs = 0.f;
#pragma unroll
            for (int ni = 0; ni < 8; ni++) {
                float p0 = exp2f(sacc[ni][rr * 2] - mnew);
                float p1 = exp2f(sacc[ni][rr * 2 + 1] - mnew);
                sacc[ni][rr * 2] = p0;
                sacc[ni][rr * 2 + 1] = p1;
                rs += p0 + p1;
            }
            rs += __shfl_xor_sync(0xffffffffu, rs, 1);
            rs += __shfl_xor_sync(0xffffffffu, rs, 2);
            lrow[rr] = lrow[rr] * corr + rs;
            mrow[rr] = mnew;
#pragma unroll
            for (int ni = 0; ni < 16; ni++) {
                O[ni][rr * 2] *= corr;
                O[ni][rr * 2 + 1] *= corr;
            }
            int prow = rb0 + g + rr * 8;
            int psw = prow & 7;
            char* Pr = (char*)sm + 98304 + prow * 128;
#pragma unroll
            for (int ni = 0; ni < 8; ni++) {
                *(__half2*)(Pr + ((ni ^ psw) << 4) + 4 * tig) =
                    __floats2half2_rn(sacc[ni][rr * 2], sacc[ni][rr * 2 + 1]);
            }
        }
        __syncwarp();
#pragma unroll
        for (int c = 0; c < 4; c++) {
            uint4 Pf;
            ldsm4(Pf, pA_base + (uint32_t)((((2 * c + hiA) ^ swA) << 4)));
            uint32_t gb = (uint32_t)((((2 * c + hiB) ^ swB) << 4));
#pragma unroll
            for (int p = 0; p < 8; p++) {
                uint4 Vf;
                ldsm4(Vf, vB_base[p] + ksb + gb);
                mma16(O[2 * p],     Pf, Vf.x, Vf.y);
                mma16(O[2 * p + 1], Pf, Vf.z, Vf.w);
            }
        }
    }

    __half* Ob = g_attn + ((size_t)(b * NQ + h)) * SEQ * HD;
#pragma unroll
    for (int rr = 0; rr < 2; rr++) {
        float inv = 1.f / lrow[rr];
        int r = q0 + rb0 + g + rr * 8;
#pragma unroll
        for (int ni = 0; ni < 16; ni++) {
            *(__half2*)&Ob[(size_t)r * HD + ni * 8 + 2 * tig] =
                __floats2half2_rn(O[ni][rr * 2] * inv, O[ni][rr * 2 + 1] * inv);
        }
    }
}

// ---------------- launch ------------------------------------------------------
extern "C" void kernel_launch(void* const* d_in, const int* in_sizes, int n_in,
                              void* d_out, int out_size) {
    const float* x  = (const float*)d_in[0];
    const float* Wq = (const float*)d_in[1];
    const float* Wk = (const float*)d_in[2];
    const float* Wv = (const float*)d_in[3];
    const float* Wo = (const float*)d_in[4];
    const float* qA = (const float*)d_in[5];
    const float* qB = (const float*)d_in[6];
    const float* kA = (const float*)d_in[7];
    const float* kB = (const float*)d_in[8];
    const float* vA = (const float*)d_in[9];
    const float* vB = (const float*)d_in[10];
    const float* oA = (const float*)d_in[11];
    const float* oB = (const float*)d_in[12];
    float* out = (float*)d_out;

    cudaFuncSetAttribute(gemm6_kernel<0>, cudaFuncAttributeMaxDynamicSharedMemorySize, GEMM_SMEM);
    cudaFuncSetAttribute(gemm6_kernel<1>, cudaFuncAttributeMaxDynamicSharedMemorySize, GEMM_SMEM);
    cudaFuncSetAttribute(flash_kernel, cudaFuncAttributeMaxDynamicSharedMemorySize, FL_SMEM);

    prep_kernel<<<13312, 256>>>(x, qA, kA, vA, Wq, Wk, Wv, Wo);

    gemm6_kernel<0><<<dim3(32, 32), 256, GEMM_SMEM>>>(qB, kB, vB, nullptr);

    flash_kernel<<<dim3(SEQ / 128, BATCH * NQ), 256, FL_SMEM>>>();

    lora_down_o2<<<512, 256>>>(oA);
    gemm6_kernel<1><<<dim3(16, 32), 256, GEMM_SMEM>>>(oB, nullptr, nullptr, out);
}

// round 16
// speedup vs baseline: 1.5479x; 1.0054x over previous
#include <cuda_runtime.h>
#include <cuda_fp16.h>
#include <math.h>
#include <stdint.h>

#define HIDDEN 2048
#define NQ 16
#define NKV 8
#define HD 128
#define SEQ 2048
#define BATCH 2
#define MROWS 4096
#define RANK 8
#define LORA_SC 2.0f
#define SM_SCALE 0.08838834764831845f
#define LOG2E 1.4426950408889634f

// ---------------- scratch (fp16 staged tensors) --------------------------------
__device__ __half g_q[8388608];      // [B][NQ][S][D]  (pre-scaled by SM_SCALE*LOG2E)
__device__ __half g_k[4194304];      // [B][NKV][S][D]
__device__ __half g_vT[4194304];     // [B][NKV][D][S]
__device__ __half g_attn[8388608];   // [B][NQ][S][D]
__device__ __half g_xr[8388608];     // fp16 x
__device__ __half g_wq[4194304];
__device__ __half g_wk[2097152];
__device__ __half g_wv[2097152];
__device__ __half g_wo[4194304];
__device__ float g_tq[MROWS * RANK];
__device__ float g_tk[MROWS * RANK];
__device__ float g_tv[MROWS * RANK];
__device__ float g_to[MROWS * RANK];
__device__ float g_cos[SEQ * 64];
__device__ float g_sin[SEQ * 64];

// ---------------- helpers -----------------------------------------------------
__device__ __forceinline__ void mma16(float* c, const uint4& a, uint32_t b0, uint32_t b1) {
    asm volatile(
        "mma.sync.aligned.m16n8k16.row.col.f32.f16.f16.f32 "
        "{%0,%1,%2,%3}, {%4,%5,%6,%7}, {%8,%9}, {%0,%1,%2,%3};\n"
        : "+f"(c[0]), "+f"(c[1]), "+f"(c[2]), "+f"(c[3])
        : "r"(a.x), "r"(a.y), "r"(a.z), "r"(a.w), "r"(b0), "r"(b1));
}

__device__ __forceinline__ uint32_t s2u(const void* p) {
    uint32_t r;
    asm("{ .reg .u64 t; cvta.to.shared.u64 t, %1; cvt.u32.u64 %0, t; }"
        : "=r"(r) : "l"(p));
    return r;
}

#define CPA16(dst, src) \
    asm volatile("cp.async.cg.shared.global [%0], [%1], 16;\n" ::"r"(dst), "l"(src))
#define CPC() asm volatile("cp.async.commit_group;\n")
#define CPW(n) asm volatile("cp.async.wait_group %0;\n" ::"n"(n))

__device__ __forceinline__ void ldsm4(uint4& d, uint32_t a) {
    asm volatile("ldmatrix.sync.aligned.m8n8.x4.shared.b16 {%0,%1,%2,%3}, [%4];\n"
                 : "=r"(d.x), "=r"(d.y), "=r"(d.z), "=r"(d.w)
                 : "r"(a));
}

__device__ __forceinline__ uint32_t h2u(__half2 h) { return *(uint32_t*)&h; }

// ---------------- merged prologue ----------------------------------------------
// blocks [0,512): LoRA down-projection for Q/K/V + x fp16 conversion (8 rows/blk)
// blocks [512, 12800): weight fp16 conversion (3145728 float4 tasks)
// blocks [12800, 13312): rope table (131072 entries)
__global__ void __launch_bounds__(256) prep_kernel(const float* __restrict__ x,
                                                   const float* __restrict__ qA,
                                                   const float* __restrict__ kA,
                                                   const float* __restrict__ vA,
                                                   const float* __restrict__ Wq,
                                                   const float* __restrict__ Wk,
                                                   const float* __restrict__ Wv,
                                                   const float* __restrict__ Wo) {
    int blk = blockIdx.x;
    int tid = threadIdx.x;
    if (blk >= 12800) {
        int idx = (blk - 12800) * 256 + tid;
        if (idx < SEQ * 64) {
            int s = idx >> 6, f = idx & 63;
            double inv = pow(10000.0, -(double)(2 * f) / 128.0);
            double ang = (double)s * inv;
            g_cos[idx] = (float)cos(ang);
            g_sin[idx] = (float)sin(ang);
        }
        return;
    }
    if (blk >= 512) {
        int i = (blk - 512) * 256 + tid;
        const float4* src;
        __half* dst;
        int j;
        if (i < 1048576) { src = (const float4*)Wq; dst = g_wq; j = i; }
        else if (i < 1572864) { src = (const float4*)Wk; dst = g_wk; j = i - 1048576; }
        else if (i < 2097152) { src = (const float4*)Wv; dst = g_wv; j = i - 1572864; }
        else { src = (const float4*)Wo; dst = g_wo; j = i - 2097152; }
        float4 v = src[j];
        __half2* d2 = (__half2*)(dst + (size_t)j * 4);
        d2[0] = __floats2half2_rn(v.x, v.y);
        d2[1] = __floats2half2_rn(v.z, v.w);
        return;
    }
    // ---- LoRA down for QKV + x conversion ----
    __shared__ float Ach[24][256];
    __shared__ float xch[8][256];
    int lane = tid & 31, w = tid >> 5;
    int m0 = blk * 8;
    float part[24];
#pragma unroll
    for (int r = 0; r < 24; r++) part[r] = 0.f;

    for (int kc = 0; kc < 8; kc++) {
        int kb = kc * 256;
#pragma unroll
        for (int i = 0; i < 6; i++) {
            int idx = i * 256 + tid;
            int r = idx >> 6, c4 = (idx & 63) << 2;
            const float* A = (r < 8) ? qA + (size_t)r * HIDDEN
                           : (r < 16) ? kA + (size_t)(r - 8) * HIDDEN
                                      : vA + (size_t)(r - 16) * HIDDEN;
            *(float4*)&Ach[r][c4] = *(const float4*)&A[kb + c4];
        }
#pragma unroll
        for (int i = 0; i < 2; i++) {
            int idx = i * 256 + tid;
            int r = idx >> 6, c4 = (idx & 63) << 2;
            float4 v = *(const float4*)&x[(size_t)(m0 + r) * HIDDEN + kb + c4];
            *(float4*)&xch[r][c4] = v;
            __half2* o = (__half2*)&g_xr[(size_t)(m0 + r) * HIDDEN + kb + c4];
            o[0] = __floats2half2_rn(v.x, v.y);
            o[1] = __floats2half2_rn(v.z, v.w);
        }
        __syncthreads();
        float xv[8];
#pragma unroll
        for (int i = 0; i < 8; i++) xv[i] = xch[w][lane + 32 * i];
#pragma unroll
        for (int r = 0; r < 24; r++) {
            float s = 0.f;
#pragma unroll
            for (int i = 0; i < 8; i++) s += xv[i] * Ach[r][lane + 32 * i];
            part[r] += s;
        }
        __syncthreads();
    }
#pragma unroll
    for (int r = 0; r < 24; r++) {
        float v = part[r];
#pragma unroll
        for (int o = 16; o > 0; o >>= 1) v += __shfl_xor_sync(0xffffffffu, v, o);
        part[r] = v;
    }
    if (lane == 0) {
        int m = m0 + w;
#pragma unroll
        for (int r = 0; r < 8; r++) {
            g_tq[m * RANK + r] = part[r];
            g_tk[m * RANK + r] = part[8 + r];
            g_tv[m * RANK + r] = part[16 + r];
        }
    }
}

// ---------------- LoRA down: O, 16 rows/block (2 per warp) ---------------------
__global__ void __launch_bounds__(256) lora_down_o2(const float* __restrict__ oA) {
    __shared__ float Ach[8][256];
    __shared__ float xch[16][256];
    int tid = threadIdx.x, lane = tid & 31, w = tid >> 5;
    int m0 = blockIdx.x * 16;
    float part[2][8];
#pragma unroll
    for (int rr = 0; rr < 2; rr++)
#pragma unroll
        for (int r = 0; r < 8; r++) part[rr][r] = 0.f;

    for (int kc = 0; kc < 8; kc++) {
        int kb = kc * 256;
#pragma unroll
        for (int i = 0; i < 2; i++) {
            int idx = i * 256 + tid;
            int r = idx >> 6, c4 = (idx & 63) << 2;
            *(float4*)&Ach[r][c4] = *(const float4*)&oA[(size_t)r * (NQ * HD) + kb + c4];
        }
#pragma unroll
        for (int i = 0; i < 4; i++) {
            int idx = i * 256 + tid;
            int r = idx >> 6, c4 = (idx & 63) << 2;
            int m = m0 + r, b = m >> 11, s = m & 2047;
            int k = kb + c4, h = k >> 7, d = k & 127;
            const __half2* src =
                (const __half2*)&g_attn[(((size_t)(b * NQ + h)) * SEQ + s) * HD + d];
            float2 f0 = __half22float2(src[0]);
            float2 f1 = __half22float2(src[1]);
            *(float4*)&xch[r][c4] = make_float4(f0.x, f0.y, f1.x, f1.y);
        }
        __syncthreads();
        float xv0[8], xv1[8];
#pragma unroll
        for (int i = 0; i < 8; i++) {
            xv0[i] = xch[2 * w][lane + 32 * i];
            xv1[i] = xch[2 * w + 1][lane + 32 * i];
        }
#pragma unroll
        for (int r = 0; r < 8; r++) {
            float s0 = 0.f, s1 = 0.f;
#pragma unroll
            for (int i = 0; i < 8; i++) {
                float a = Ach[r][lane + 32 * i];
                s0 += xv0[i] * a;
                s1 += xv1[i] * a;
            }
            part[0][r] += s0;
            part[1][r] += s1;
        }
        __syncthreads();
    }
#pragma unroll
    for (int rr = 0; rr < 2; rr++) {
#pragma unroll
        for (int r = 0; r < 8; r++) {
            float v = part[rr][r];
#pragma unroll
            for (int o = 16; o > 0; o >>= 1) v += __shfl_xor_sync(0xffffffffu, v, o);
            part[rr][r] = v;
        }
        if (lane == 0) {
            int m = m0 + 2 * w + rr;
#pragma unroll
            for (int r = 0; r < 8; r++) g_to[m * RANK + r] = part[rr][r];
        }
    }
}

// ---------------- fp16 GEMM: cp.async + ldmatrix + m16n8k16 (R7 config) --------
#define GEMM_SMEM 65536

template <int IS_O>
__global__ void __launch_bounds__(256, 2) gemm6_kernel(
    const float* __restrict__ qBp, const float* __restrict__ kBp,
    const float* __restrict__ vBp, float* __restrict__ Out) {
    extern __shared__ uint32_t smw[];
    const int tid = threadIdx.x, lane = tid & 31, wid = tid >> 5;
    const int g = lane >> 2, tig = lane & 3;
    const int wm = (wid & 3) * 32, wn = (wid >> 2) * 64;
    const int m0 = blockIdx.y * 128;
    const int nb = blockIdx.x;

    const __half* W;
    const float *U, *T;
    int which, nrel0;
    if (IS_O) {
        which = 3; nrel0 = nb * 128;
        W = g_wo + (size_t)nrel0 * HIDDEN; U = qBp + nrel0 * RANK; T = g_to;
    } else if (nb < 16) {
        which = 0; nrel0 = nb * 128;
        W = g_wq + (size_t)nrel0 * HIDDEN; U = qBp + nrel0 * RANK; T = g_tq;
    } else if (nb < 24) {
        which = 1; nrel0 = nb * 128 - 2048;
        W = g_wk + (size_t)nrel0 * HIDDEN; U = kBp + nrel0 * RANK; T = g_tk;
    } else {
        which = 2; nrel0 = nb * 128 - 3072;
        W = g_wv + (size_t)nrel0 * HIDDEN; U = vBp + nrel0 * RANK; T = g_tv;
    }

    const uint32_t smb = s2u(smw);

    const int fr = tid >> 1;
    const int fj0 = (tid & 1) * 2;
    const int fsw = (fr >> 1) & 3;
    const __half* srcB = W + (size_t)fr * HIDDEN;
    size_t aoff;
    if (IS_O) {
        int m = m0 + fr, b = m >> 11, s = m & 2047;
        aoff = (((size_t)(b * NQ)) * SEQ + s) * HD;
    } else {
        aoff = (size_t)(m0 + fr) * HIDDEN;
    }

    auto fill = [&](int st, int kc) {
        uint32_t dA = smb + (uint32_t)st * 8192u + (uint32_t)fr * 64u;
#pragma unroll
        for (int u = 0; u < 2; u++) {
            int j = fj0 + u;
            int k = kc * 32 + j * 8;
            const char* sA;
            if (IS_O) {
                int hh = k >> 7, dd = k & 127;
                sA = (const char*)(g_attn + aoff + (size_t)hh * SEQ * HD + dd);
            } else {
                sA = (const char*)(g_xr + aoff + k);
            }
            uint32_t dsw = (uint32_t)((j ^ fsw) << 4);
            CPA16(dA + dsw, sA);
            CPA16(dA + 32768u + dsw, (const char*)(srcB + k));
        }
    };

    const int rowAoff = (lane & 7) + ((lane >> 3) & 1) * 8;
    const int hiA = lane >> 4;
    const int swA = (rowAoff >> 1) & 3;
    const int rowBoff = (lane & 7) + ((lane >> 4) << 3);
    const int hiB = (lane >> 3) & 1;
    const int swB = (rowBoff >> 1) & 3;
    uint32_t aAddr[2], bAddr[4];
#pragma unroll
    for (int mt = 0; mt < 2; mt++)
        aAddr[mt] = smb + (uint32_t)((wm + mt * 16 + rowAoff) * 64);
#pragma unroll
    for (int p = 0; p < 4; p++)
        bAddr[p] = smb + 32768u + (uint32_t)((wn + p * 16 + rowBoff) * 64);

    float acc[2][8][4];
#pragma unroll
    for (int a = 0; a < 2; a++)
#pragma unroll
        for (int b2 = 0; b2 < 8; b2++)
#pragma unroll
            for (int c = 0; c < 4; c++) acc[a][b2][c] = 0.f;

    fill(0, 0); CPC();
    fill(1, 1); CPC();
    fill(2, 2); CPC();

    const int NKC = HIDDEN / 32;   // 64
    for (int kc = 0; kc < NKC; kc++) {
        CPW(2);
        __syncthreads();
        if (kc + 3 < NKC) { fill((kc + 3) & 3, kc + 3); CPC(); } else { CPC(); }
        uint32_t sb = (uint32_t)((kc & 3) * 8192);
#pragma unroll
        for (int c = 0; c < 2; c++) {
            uint4 Af0, Af1;
            uint32_t ga = (uint32_t)((((2 * c + hiA) ^ swA) << 4));
            ldsm4(Af0, aAddr[0] + sb + ga);
            ldsm4(Af1, aAddr[1] + sb + ga);
            uint32_t gb = (uint32_t)((((2 * c + hiB) ^ swB) << 4));
#pragma unroll
            for (int p = 0; p < 4; p++) {
                uint4 Bf;
                ldsm4(Bf, bAddr[p] + sb + gb);
                mma16(acc[0][2 * p],     Af0, Bf.x, Bf.y);
                mma16(acc[0][2 * p + 1], Af0, Bf.z, Bf.w);
                mma16(acc[1][2 * p],     Af1, Bf.x, Bf.y);
                mma16(acc[1][2 * p + 1], Af1, Bf.z, Bf.w);
            }
        }
    }

    // LoRA rank-8 tail
    __syncthreads();
    {
        int r = tid & 127;
        const float* src;
        float sc;
        uint32_t base;
        if (tid < 128) { src = T + (size_t)(m0 + r) * RANK; sc = 1.f; base = 0; }
        else           { src = U + (size_t)r * RANK; sc = LORA_SC; base = 8192; }
        __half2 h0 = __floats2half2_rn(src[0] * sc, src[1] * sc);
        __half2 h1 = __floats2half2_rn(src[2] * sc, src[3] * sc);
        __half2 h2 = __floats2half2_rn(src[4] * sc, src[5] * sc);
        __half2 h3 = __floats2half2_rn(src[6] * sc, src[7] * sc);
        int sw = (r >> 1) & 3;
        uint32_t w0 = base + r * 16 + ((0 ^ sw) << 2);
        uint32_t w1 = base + r * 16 + ((1 ^ sw) << 2);
        smw[w0 + 0] = h2u(h0); smw[w0 + 1] = h2u(h1);
        smw[w0 + 2] = h2u(h2); smw[w0 + 3] = h2u(h3);
        smw[w1 + 0] = 0; smw[w1 + 1] = 0; smw[w1 + 2] = 0; smw[w1 + 3] = 0;
    }
    __syncthreads();
    {
        uint4 Af0, Af1;
        uint32_t ga = (uint32_t)(((hiA ^ swA) << 4));
        ldsm4(Af0, aAddr[0] + ga);
        ldsm4(Af1, aAddr[1] + ga);
        uint32_t gb = (uint32_t)(((hiB ^ swB) << 4));
#pragma unroll
        for (int p = 0; p < 4; p++) {
            uint4 Bf;
            ldsm4(Bf, bAddr[p] + gb);
            mma16(acc[0][2 * p],     Af0, Bf.x, Bf.y);
            mma16(acc[0][2 * p + 1], Af0, Bf.z, Bf.w);
            mma16(acc[1][2 * p],     Af1, Bf.x, Bf.y);
            mma16(acc[1][2 * p + 1], Af1, Bf.z, Bf.w);
        }
    }

    // epilogue
#pragma unroll
    for (int mt = 0; mt < 2; mt++) {
#pragma unroll
        for (int rr = 0; rr < 2; rr++) {
            int m = m0 + wm + mt * 16 + g + rr * 8;
            int s = m & 2047, b = m >> 11;
#pragma unroll
            for (int ni = 0; ni < 8; ni++) {
                int nrel = nrel0 + wn + ni * 8 + 2 * tig;
                float v0 = acc[mt][ni][rr * 2 + 0];
                float v1 = acc[mt][ni][rr * 2 + 1];
                int d = nrel & 127;
                if (which <= 1) {
                    int f = d >> 1;
                    float c = g_cos[s * 64 + f], sn = g_sin[s * 64 + f];
                    float t0 = v0 * c - v1 * sn;
                    v1 = v0 * sn + v1 * c;
                    v0 = t0;
                }
                if (which == 3) {
                    *(float2*)&Out[(size_t)m * HIDDEN + nrel] = make_float2(v0, v1);
                } else if (which == 0) {
                    *(__half2*)&g_q[(((size_t)(b * NQ + (nrel >> 7))) * SEQ + s) * HD + d] =
                        __floats2half2_rn(v0 * (SM_SCALE * LOG2E), v1 * (SM_SCALE * LOG2E));
                } else if (which == 1) {
                    *(__half2*)&g_k[(((size_t)(b * NKV + (nrel >> 7))) * SEQ + s) * HD + d] =
                        __floats2half2_rn(v0, v1);
                } else {
                    __half* vb = g_vT + (((size_t)(b * NKV + (nrel >> 7))) * HD + d) * SEQ;
                    vb[s] = __float2half_rn(v0);
                    vb[SEQ + s] = __float2half_rn(v1);
                }
            }
        }
    }
}

// ---------------- fp16 flash attention (exp2-domain softmax) -------------------
#define FL_SMEM 114688

__global__ void __launch_bounds__(256, 2) flash_kernel() {
    extern __shared__ uint32_t sm[];
    const int tid = threadIdx.x, lane = tid & 31, wid = tid >> 5;
    const int g = lane >> 2, tig = lane & 3;
    int qb = (gridDim.x - 1) - blockIdx.x;
    int bh = blockIdx.y;
    int b = bh >> 4, h = bh & 15, kvh = h >> 1;
    const __half* Qb = g_q + ((size_t)(b * NQ + h)) * SEQ * HD;
    const __half* Kb = g_k + ((size_t)(b * NKV + kvh)) * SEQ * HD;
    const __half* Vb = g_vT + ((size_t)(b * NKV + kvh)) * HD * SEQ;
    int q0 = qb * 128, rb0 = wid * 16;
    const uint32_t smb = s2u(sm);

    const int rowAoff = (lane & 7) + ((lane >> 3) & 1) * 8;
    const int hiA = lane >> 4;
    const int swA = rowAoff & 7;
    const int rowBoff = (lane & 7) + ((lane >> 4) << 3);
    const int hiB = (lane >> 3) & 1;
    const int swB = rowBoff & 7;

    const uint32_t qA_base = smb + (uint32_t)((rb0 + rowAoff) * 256);
    const uint32_t pA_base = smb + 98304u + (uint32_t)((rb0 + rowAoff) * 128);
    uint32_t kB_base[4], vB_base[8];
#pragma unroll
    for (int p = 0; p < 4; p++)
        kB_base[p] = smb + 32768u + (uint32_t)((p * 16 + rowBoff) * 256);
#pragma unroll
    for (int p = 0; p < 8; p++)
        vB_base[p] = smb + 65536u + (uint32_t)((p * 16 + rowBoff) * 128);

#pragma unroll
    for (int i = 0; i < 8; i++) {
        int gid = i * 256 + tid;
        int r = gid >> 4, j = gid & 15;
        CPA16(smb + (uint32_t)(r * 256 + ((j ^ (r & 7)) << 4)),
              (const char*)(Qb + (size_t)(q0 + r) * HD + j * 8));
    }
    CPC();
    auto fillKV = [&](int kt, int st) {
        int k0 = kt * 64;
        uint32_t kst = smb + 32768u + (uint32_t)st * 16384u;
        uint32_t vst = smb + 65536u + (uint32_t)st * 16384u;
#pragma unroll
        for (int i = 0; i < 4; i++) {
            int gid = i * 256 + tid;
            int r = gid >> 4, j = gid & 15;
            CPA16(kst + (uint32_t)(r * 256 + ((j ^ (r & 7)) << 4)),
                  (const char*)(Kb + (size_t)(k0 + r) * HD + j * 8));
        }
#pragma unroll
        for (int i = 0; i < 4; i++) {
            int gid = i * 256 + tid;
            int rv = gid >> 3, jv = gid & 7;
            CPA16(vst + (uint32_t)(rv * 128 + ((jv ^ (rv & 7)) << 4)),
                  (const char*)(Vb + (size_t)rv * SEQ + k0 + jv * 8));
        }
    };
    fillKV(0, 0);
    CPC();

    float O[16][4];
#pragma unroll
    for (int i = 0; i < 16; i++)
#pragma unroll
        for (int j = 0; j < 4; j++) O[i][j] = 0.f;
    float mrow[2] = {-1e30f, -1e30f}, lrow[2] = {0.f, 0.f};

    int ktmax = 2 * qb + 1;
    for (int kt = 0; kt <= ktmax; kt++) {
        __syncthreads();
        if (kt < ktmax) { fillKV(kt + 1, (kt + 1) & 1); CPC(); } else { CPC(); }
        CPW(1);
        __syncthreads();
        uint32_t ksb = (kt & 1) ? 16384u : 0u;
        int k0 = kt * 64;

        float sacc[8][4];
#pragma unroll
        for (int i = 0; i < 8; i++)
#pragma unroll
            for (int j = 0; j < 4; j++) sacc[i][j] = 0.f;
#pragma unroll
        for (int c = 0; c < 8; c++) {
            uint4 Qf;
            ldsm4(Qf, qA_base + (uint32_t)((((2 * c + hiA) ^ swA) << 4)));
            uint32_t gb = (uint32_t)((((2 * c + hiB) ^ swB) << 4));
#pragma unroll
            for (int p = 0; p < 4; p++) {
                uint4 Kf;
                ldsm4(Kf, kB_base[p] + ksb + gb);
                mma16(sacc[2 * p],     Qf, Kf.x, Kf.y);
                mma16(sacc[2 * p + 1], Qf, Kf.z, Kf.w);
            }
        }
        if (kt >= 2 * qb) {
#pragma unroll
            for (int ni = 0; ni < 8; ni++)
#pragma unroll
                for (int j = 0; j < 4; j++) {
                    int col = k0 + ni * 8 + 2 * tig + (j & 1);
                    int row = q0 + rb0 + g + ((j >> 1) << 3);
                    if (col > row) sacc[ni][j] = -1e30f;
                }
        }
#pragma unroll
        for (int rr = 0; rr < 2; rr++) {
            float mx = -1e30f;
#pragma unroll
            for (int ni = 0; ni < 8; ni++)
                mx = fmaxf(mx, fmaxf(sacc[ni][rr * 2], sacc[ni][rr * 2 + 1]));
            mx = fmaxf(mx, __shfl_xor_sync(0xffffffffu, mx, 1));
            mx = fmaxf(mx, __shfl_xor_sync(0xffffffffu, mx, 2));
            float mnew = fmaxf(mrow[rr], mx);
            float corr = exp2f(mrow[rr] - mnew);
            float rs = 0.f;
#pragma unroll
            for (int ni = 0; ni < 8; ni++) {
                float p0 = exp2f(sacc[ni][rr * 2] - mnew);
                float p1 = exp2f(sacc[ni][rr * 2 + 1] - mnew);
                sacc[ni][rr * 2] = p0;
                sacc[ni][rr * 2 + 1] = p1;
                rs += p0 + p1;
            }
            rs += __shfl_xor_sync(0xffffffffu, rs, 1);
            rs += __shfl_xor_sync(0xffffffffu, rs, 2);
            lrow[rr] = lrow[rr] * corr + rs;
            mrow[rr] = mnew;
#pragma unroll
            for (int ni = 0; ni < 16; ni++) {
                O[ni][rr * 2] *= corr;
                O[ni][rr * 2 + 1] *= corr;
            }
            int prow = rb0 + g + rr * 8;
            int psw = prow & 7;
            char* Pr = (char*)sm + 98304 + prow * 128;
#pragma unroll
            for (int ni = 0; ni < 8; ni++) {
                *(__half2*)(Pr + ((ni ^ psw) << 4) + 4 * tig) =
                    __floats2half2_rn(sacc[ni][rr * 2], sacc[ni][rr * 2 + 1]);
            }
        }
        __syncwarp();
#pragma unroll
        for (int c = 0; c < 4; c++) {
            uint4 Pf;
            ldsm4(Pf, pA_base + (uint32_t)((((2 * c + hiA) ^ swA) << 4)));
            uint32_t gb = (uint32_t)((((2 * c + hiB) ^ swB) << 4));
#pragma unroll
            for (int p = 0; p < 8; p++) {
                uint4 Vf;
                ldsm4(Vf, vB_base[p] + ksb + gb);
                mma16(O[2 * p],     Pf, Vf.x, Vf.y);
                mma16(O[2 * p + 1], Pf, Vf.z, Vf.w);
            }
        }
    }

    __half* Ob = g_attn + ((size_t)(b * NQ + h)) * SEQ * HD;
#pragma unroll
    for (int rr = 0; rr < 2; rr++) {
        float inv = 1.f / lrow[rr];
        int r = q0 + rb0 + g + rr * 8;
#pragma unroll
        for (int ni = 0; ni < 16; ni++) {
            *(__half2*)&Ob[(size_t)r * HD + ni * 8 + 2 * tig] =
                __floats2half2_rn(O[ni][rr * 2] * inv, O[ni][rr * 2 + 1] * inv);
        }
    }
}

// ---------------- launch ------------------------------------------------------
extern "C" void kernel_launch(void* const* d_in, const int* in_sizes, int n_in,
                              void* d_out, int out_size) {
    const float* x  = (const float*)d_in[0];
    const float* Wq = (const float*)d_in[1];
    const float* Wk = (const float*)d_in[2];
    const float* Wv = (const float*)d_in[3];
    const float* Wo = (const float*)d_in[4];
    const float* qA = (const float*)d_in[5];
    const float* qB = (const float*)d_in[6];
    const float* kA = (const float*)d_in[7];
    const float* kB = (const float*)d_in[8];
    const float* vA = (const float*)d_in[9];
    const float* vB = (const float*)d_in[10];
    const float* oA = (const float*)d_in[11];
    const float* oB = (const float*)d_in[12];
    float* out = (float*)d_out;

    cudaFuncSetAttribute(gemm6_kernel<0>, cudaFuncAttributeMaxDynamicSharedMemorySize, GEMM_SMEM);
    cudaFuncSetAttribute(gemm6_kernel<1>, cudaFuncAttributeMaxDynamicSharedMemorySize, GEMM_SMEM);
    cudaFuncSetAttribute(flash_kernel, cudaFuncAttributeMaxDynamicSharedMemorySize, FL_SMEM);

    prep_kernel<<<13312, 256>>>(x, qA, kA, vA, Wq, Wk, Wv, Wo);

    gemm6_kernel<0><<<dim3(32, 32), 256, GEMM_SMEM>>>(qB, kB, vB, nullptr);

    flash_kernel<<<dim3(SEQ / 128, BATCH * NQ), 256, FL_SMEM>>>();

    lora_down_o2<<<256, 256>>>(oA);
    gemm6_kernel<1><<<dim3(16, 32), 256, GEMM_SMEM>>>(oB, nullptr, nullptr, out);
}